// round 12
// baseline (speedup 1.0000x reference)
#include <cuda_runtime.h>
#include <cuda_fp16.h>
#include <math_constants.h>
#include <cstdint>

// ---------------------------------------------------------------------------
// HigherOrderAttention — R12:
//   * attn reverted to R10 math (fp32 S accumulators — R11 fp16-acc failed
//     accuracy)
//   * rmsnorm fused into the QKV GEMM epilogue (each 64x64 C tile = one head
//     segment x 64 tokens; rms + fp16 store in-block, qkv scratch eliminated)
// ---------------------------------------------------------------------------

#define TOK_B   2
#define SEQ     192
#define DIMM    512
#define HEADS   8
#define DH      64
#define BHD     (TOK_B * HEADS)        // 16
#define QKV_C   2560
#define ROWS    (TOK_B * SEQ)          // 384
#define KSPLIT  6
#define KRANGE  (SEQ / KSPLIT)         // 32
#define ITILE   64
#define NWARP   4
#define NTHR    (NWARP * 32)           // 128
#define NJC     (SEQ / 32)             // 6

#define M_LOG2  7.2134752f             // 5 * log2(e)
#define QSCALE  0.18033688f            // 0.125 * log2(e)

// Scratch (device globals)
__device__ __half g_hq  [BHD * SEQ * DH];
__device__ __half g_hk1 [BHD * SEQ * DH];
__device__ __half g_hk2 [BHD * SEQ * DH];
__device__ __half g_hv1 [BHD * SEQ * DH];
__device__ __half g_hv2 [BHD * SEQ * DH];
__device__ float  g_pacc[KSPLIT * BHD * SEQ * DH];
__device__ float  g_pl  [KSPLIT * BHD * SEQ];
__device__ __half g_th  [ROWS * DIMM],  g_tl  [ROWS * DIMM];
__device__ __half g_wqh [QKV_C * DIMM], g_wql [QKV_C * DIMM];
__device__ __half g_woh [DIMM * DIMM],  g_wol [DIMM * DIMM];
__device__ __half g_ah  [ROWS * DIMM],  g_al  [ROWS * DIMM];

// ---------------------------------------------------------------------------
__device__ __forceinline__ void mma16816(float c[4],
                                         unsigned a0, unsigned a1,
                                         unsigned a2, unsigned a3,
                                         unsigned b0, unsigned b1)
{
    asm volatile(
        "mma.sync.aligned.m16n8k16.row.col.f32.f16.f16.f32 "
        "{%0,%1,%2,%3},{%4,%5,%6,%7},{%8,%9},{%0,%1,%2,%3};\n"
        : "+f"(c[0]), "+f"(c[1]), "+f"(c[2]), "+f"(c[3])
        : "r"(a0), "r"(a1), "r"(a2), "r"(a3), "r"(b0), "r"(b1));
}

__device__ __forceinline__ void ldsm_x4(unsigned r[4], const __half* p)
{
    unsigned sa = (unsigned)__cvta_generic_to_shared(p);
    asm volatile("ldmatrix.sync.aligned.m8n8.x4.shared.b16 {%0,%1,%2,%3}, [%4];"
                 : "=r"(r[0]), "=r"(r[1]), "=r"(r[2]), "=r"(r[3]) : "r"(sa));
}

__device__ __forceinline__ unsigned hmul2u(unsigned a, __half2 b)
{
    __half2 av = *reinterpret_cast<__half2*>(&a);
    __half2 r  = __hmul2(av, b);
    return *reinterpret_cast<unsigned*>(&r);
}

__device__ __forceinline__ __half2 u2h2(unsigned a)
{
    return *reinterpret_cast<__half2*>(&a);
}

__device__ __forceinline__ unsigned p2exp(float a, float b)
{
    __half2 h = __floats2half2_rn(a, b);
    unsigned x = *reinterpret_cast<unsigned*>(&h);
    unsigned r;
    asm("ex2.approx.f16x2 %0, %1;" : "=r"(r) : "r"(x));
    return r;
}

// ---------------------------------------------------------------------------
// Fused fp32 -> (hi,lo) fp16 split for 3 arrays.
// ---------------------------------------------------------------------------
__device__ __forceinline__ void split_quad(const float* __restrict__ x,
                                           __half* __restrict__ hi,
                                           __half* __restrict__ lo, int i)
{
    float4 v = ((const float4*)x)[i];
    __half hx = __float2half_rn(v.x), hy = __float2half_rn(v.y);
    __half hz = __float2half_rn(v.z), hw = __float2half_rn(v.w);
    ((__half2*)hi)[2 * i]     = __halves2half2(hx, hy);
    ((__half2*)hi)[2 * i + 1] = __halves2half2(hz, hw);
    ((__half2*)lo)[2 * i]     = __halves2half2(
        __float2half_rn(v.x - __half2float(hx)),
        __float2half_rn(v.y - __half2float(hy)));
    ((__half2*)lo)[2 * i + 1] = __halves2half2(
        __float2half_rn(v.z - __half2float(hz)),
        __float2half_rn(v.w - __half2float(hw)));
}

#define N0Q (ROWS * DIMM / 4)
#define N1Q (QKV_C * DIMM / 4)
#define N2Q (DIMM * DIMM / 4)

__global__ __launch_bounds__(256) void split3_fp16(
    const float* __restrict__ x0, __half* __restrict__ h0, __half* __restrict__ l0,
    const float* __restrict__ x1, __half* __restrict__ h1, __half* __restrict__ l1,
    const float* __restrict__ x2, __half* __restrict__ h2, __half* __restrict__ l2)
{
    int i = blockIdx.x * 256 + threadIdx.x;
    if (i < N0Q) {
        split_quad(x0, h0, l0, i);
    } else if (i < N0Q + N1Q) {
        split_quad(x1, h1, l1, i - N0Q);
    } else if (i < N0Q + N1Q + N2Q) {
        split_quad(x2, h2, l2, i - N0Q - N1Q);
    }
}

// ---------------------------------------------------------------------------
// Shared GEMM mainloop (64x64 tile, hi/lo fp16 operands, ldmatrix + double
// buffer). Produces per-thread c[4][4].
// ---------------------------------------------------------------------------
#define GS 40   // smem row stride in halves

struct GemmCtx {
    int wm, wn, g, tg;
};

__device__ __forceinline__ void gemm_mainloop(
    __half* smbase,                     // [2][4][64*GS]
    const __half* Ah_, const __half* Al_,
    const __half* Bh_, const __half* Bl_,
    int m0, int n0, int K, float c[4][4], GemmCtx& cx)
{
    const int t    = threadIdx.x;
    const int warp = t >> 5;
    const int lane = t & 31;
    cx.g  = lane >> 2;
    cx.tg = lane & 3;
    cx.wm = warp >> 1;
    cx.wn = warp & 1;

    const int lrow = t >> 2;
    const int lc8  = (t & 3) * 8;

    const int a_off = (cx.wm * 16 + (lane & 15)) * GS + 8 * (lane >> 4);
    const int b_row = cx.wn * 32 + (lane & 7) + ((lane >> 4) & 1) * 8;
    const int b_c8  = ((lane >> 3) & 1) * 8;

#pragma unroll
    for (int a = 0; a < 4; ++a)
#pragma unroll
        for (int b = 0; b < 4; ++b) c[a][b] = 0.f;

    const int NIT = K >> 5;
    const int BUF = 4 * 64 * GS;
    uint4 ra, rb, rc, rd;

    {
        size_t ga = (size_t)(m0 + lrow) * K + lc8;
        size_t gb = (size_t)(n0 + lrow) * K + lc8;
        ra = *(const uint4*)(Ah_ + ga);
        rb = *(const uint4*)(Al_ + ga);
        rc = *(const uint4*)(Bh_ + gb);
        rd = *(const uint4*)(Bl_ + gb);
        __half* p = smbase + lrow * GS + lc8;
        *(uint4*)(p)               = ra;
        *(uint4*)(p + 64 * GS)     = rb;
        *(uint4*)(p + 2 * 64 * GS) = rc;
        *(uint4*)(p + 3 * 64 * GS) = rd;
    }
    __syncthreads();

#pragma unroll 1
    for (int it = 0; it < NIT; ++it) {
        const int cur = it & 1;

        if (it + 1 < NIT) {
            size_t ga = (size_t)(m0 + lrow) * K + (it + 1) * 32 + lc8;
            size_t gb = (size_t)(n0 + lrow) * K + (it + 1) * 32 + lc8;
            ra = *(const uint4*)(Ah_ + ga);
            rb = *(const uint4*)(Al_ + ga);
            rc = *(const uint4*)(Bh_ + gb);
            rd = *(const uint4*)(Bl_ + gb);
        }

        const __half* Ahs = smbase + cur * BUF;
        const __half* Als = Ahs + 64 * GS;
        const __half* Bhs = Ahs + 2 * 64 * GS;
        const __half* Bls = Ahs + 3 * 64 * GS;

#pragma unroll
        for (int kc = 0; kc < 2; ++kc) {
            const int ko = kc * 16;
            unsigned ah[4], al[4];
            ldsm_x4(ah, Ahs + a_off + ko);
            ldsm_x4(al, Als + a_off + ko);
#pragma unroll
            for (int p = 0; p < 2; ++p) {
                unsigned bh[4], bl[4];
                const int bo = (b_row + p * 16) * GS + ko + b_c8;
                ldsm_x4(bh, Bhs + bo);
                ldsm_x4(bl, Bls + bo);
                mma16816(c[2 * p],     ah[0], ah[1], ah[2], ah[3], bh[0], bh[1]);
                mma16816(c[2 * p],     ah[0], ah[1], ah[2], ah[3], bl[0], bl[1]);
                mma16816(c[2 * p],     al[0], al[1], al[2], al[3], bh[0], bh[1]);
                mma16816(c[2 * p + 1], ah[0], ah[1], ah[2], ah[3], bh[2], bh[3]);
                mma16816(c[2 * p + 1], ah[0], ah[1], ah[2], ah[3], bl[2], bl[3]);
                mma16816(c[2 * p + 1], al[0], al[1], al[2], al[3], bh[2], bh[3]);
            }
        }

        if (it + 1 < NIT) {
            __half* p = smbase + (cur ^ 1) * BUF + lrow * GS + lc8;
            *(uint4*)(p)               = ra;
            *(uint4*)(p + 64 * GS)     = rb;
            *(uint4*)(p + 2 * 64 * GS) = rc;
            *(uint4*)(p + 3 * 64 * GS) = rd;
            __syncthreads();
        }
    }
}

// ---------------------------------------------------------------------------
// Plain NT GEMM (used for the output projection): C fp32 to global.
// ---------------------------------------------------------------------------
__global__ __launch_bounds__(256) void gemm_nt_tch(
    const __half* __restrict__ Ah_, const __half* __restrict__ Al_,
    const __half* __restrict__ Bh_, const __half* __restrict__ Bl_,
    float* __restrict__ C, int M, int N, int K)
{
    __shared__ __half sm[2][4][64 * GS];
    float c[4][4];
    GemmCtx cx;
    gemm_mainloop(&sm[0][0][0], Ah_, Al_, Bh_, Bl_,
                  blockIdx.y * 64, blockIdx.x * 64, K, c, cx);

    const int row0 = blockIdx.y * 64 + cx.wm * 16 + cx.g;
    const int row1 = row0 + 8;
#pragma unroll
    for (int nt = 0; nt < 4; ++nt) {
        const int col = blockIdx.x * 64 + cx.wn * 32 + nt * 8 + 2 * cx.tg;
        *(float2*)(C + (size_t)row0 * N + col) = make_float2(c[nt][0], c[nt][1]);
        *(float2*)(C + (size_t)row1 * N + col) = make_float2(c[nt][2], c[nt][3]);
    }
}

// ---------------------------------------------------------------------------
// QKV GEMM with fused rmsnorm epilogue. Each block's 64x64 C tile is exactly
// one head segment (q/k1/k2/v1/v2, head h) x 64 tokens. Stage C in smem,
// per-row rms reduce (warp shfl, same order as the old standalone kernel),
// write fp16 to the per-tensor [bh, n, d] layout.
// ---------------------------------------------------------------------------
__global__ __launch_bounds__(256) void gemm_qkv_rms(
    const __half* __restrict__ Ah_, const __half* __restrict__ Al_,
    const __half* __restrict__ Bh_, const __half* __restrict__ Bl_,
    const float* __restrict__ qw,  const float* __restrict__ k1w,
    const float* __restrict__ k2w, const float* __restrict__ v1w,
    const float* __restrict__ v2w,
    __half* __restrict__ hq,  __half* __restrict__ hk1, __half* __restrict__ hk2,
    __half* __restrict__ hv1, __half* __restrict__ hv2)
{
    __shared__ __half sm[2][4][64 * GS];   // 40 KB; reused by epilogue
    float c[4][4];
    GemmCtx cx;
    const int m0 = blockIdx.y * 64;
    const int n0 = blockIdx.x * 64;
    gemm_mainloop(&sm[0][0][0], Ah_, Al_, Bh_, Bl_, m0, n0, DIMM, c, cx);

    // ---- stage C tile to smem as [64][68] fp32 ----------------------------
    __syncthreads();                      // mainloop smem reads done
    float* smf = (float*)&sm[0][0][0];    // 64*68*4 = 17408 B <= 40960 B
#pragma unroll
    for (int nt = 0; nt < 4; ++nt) {
        const int col  = cx.wn * 32 + nt * 8 + 2 * cx.tg;
        const int row0 = cx.wm * 16 + cx.g;
        *(float2*)(smf + row0 * 68 + col)       = make_float2(c[nt][0], c[nt][1]);
        *(float2*)(smf + (row0 + 8) * 68 + col) = make_float2(c[nt][2], c[nt][3]);
    }
    __syncthreads();

    // ---- select output tensor / weight / scale from n0 --------------------
    __half* dst;
    const float* w;
    float scale = 1.0f;
    int h;
    if (n0 < 512) {
        h = n0 >> 6;  dst = hq;  w = qw;  scale = QSCALE;
    } else if (n0 < 1536) {
        int off = n0 - 512;
        h = off >> 7;
        dst = (off & 64) ? hk2 : hk1;
        w   = (off & 64) ? k2w : k1w;
    } else {
        int off = n0 - 1536;
        h = off >> 7;
        dst = (off & 64) ? hv2 : hv1;
        w   = (off & 64) ? v2w : v1w;
    }

    // ---- rms per row: 8 warps x 8 rows, identical math to old kernel ------
    const int warp = threadIdx.x >> 5;
    const int lane = threadIdx.x & 31;
    const float w0 = w[lane];
    const float w1 = w[lane + 32];

#pragma unroll
    for (int rr = 0; rr < 8; ++rr) {
        const int r    = warp * 8 + rr;
        const int grow = m0 + r;              // global token row
        const int b    = grow / SEQ;
        const int n    = grow % SEQ;

        float x0 = smf[r * 68 + lane];
        float x1 = smf[r * 68 + lane + 32];
        float ss = x0 * x0 + x1 * x1;
#pragma unroll
        for (int o = 16; o >= 1; o >>= 1)
            ss += __shfl_xor_sync(0xffffffffu, ss, o);
        float inv = rsqrtf(ss * (1.0f / 64.0f) + 1.1920929e-07f) * scale;

        __half* yp = dst + ((size_t)(b * HEADS + h) * SEQ + n) * DH;
        yp[lane]      = __float2half(x0 * inv * w0);
        yp[lane + 32] = __float2half(x1 * inv * w1);
    }
}

// ---------------------------------------------------------------------------
// Tensor-core attention (identical to R10: fp32 S acc, static-max softmax,
// kk-loop unrolled x2).
// ---------------------------------------------------------------------------
#define K1_STRIDE 72
#define SM_K1   (SEQ * K1_STRIDE)
#define SM_V1T  (DH * 200)
#define SM_Q    (ITILE * DH)
#define SM_K2   (KRANGE * DH)
#define SM_V2   (KRANGE * DH)
#define ATTN_SMEM_HALVES (SM_K1 + SM_V1T + SM_Q + SM_K2 + SM_V2)
#define ATTN_SMEM_BYTES  (ATTN_SMEM_HALVES * 2)

__global__ __launch_bounds__(NTHR, 2) void attn_mma(
    const __half* __restrict__ hq,  const __half* __restrict__ hk1,
    const __half* __restrict__ hk2, const __half* __restrict__ hv1,
    const __half* __restrict__ hv2,
    float* __restrict__ pacc, float* __restrict__ pl)
{
    extern __shared__ __align__(16) __half smh[];
    __half*  k1s  = smh;
    __half*  v1t  = k1s + SM_K1;
    __half*  qs   = v1t + SM_V1T;
    __half2* k2t2 = (__half2*)(qs + SM_Q);
    __half*  v2t  = qs + SM_Q + SM_K2;

    const int split = blockIdx.x;
    const int i0    = blockIdx.y * ITILE;
    const int bh    = blockIdx.z;
    const int t     = threadIdx.x;
    const int kbeg  = split * KRANGE;

    const __half* k1b = hk1 + bh * SEQ * DH;
    const __half* v1b = hv1 + bh * SEQ * DH;
    const __half* k2b = hk2 + (bh * SEQ + kbeg) * DH;
    const __half* v2b = hv2 + (bh * SEQ + kbeg) * DH;
    const __half* qb  = hq  + (bh * SEQ + i0) * DH;

    for (int e = t; e < SEQ * DH; e += NTHR) {
        int j = e >> 6, d = e & 63;
        k1s[j * K1_STRIDE + d] = k1b[e];
        v1t[d * 200 + j]       = v1b[e];
    }
    for (int e = t; e < ITILE * DH; e += NTHR) qs[e] = qb[e];
    for (int e = t; e < KRANGE * 32; e += NTHR) {
        int kk = e >> 5, r = e & 31;
        int tg_ = r >> 3, s = r & 7;
        int col = (s >> 1) * 16 + (s & 1) * 8 + tg_ * 2;
        k2t2[e] = *(const __half2*)(k2b + kk * DH + col);
    }
    for (int e = t; e < KRANGE * 64; e += NTHR) {
        int kk = e >> 6, r = e & 63;
        int g_ = r >> 3, nt = r & 7;
        v2t[e] = v2b[kk * DH + nt * 8 + g_];
    }
    __syncthreads();

    const int warp = t >> 5;
    const int lane = t & 31;
    const int g    = lane >> 2;
    const int tg   = lane & 3;

    const unsigned BONES = 0x3C003C00u;

    unsigned qa[4][4];
    {
        const __half* qr0 = qs + (warp * 16 + g) * DH;
        const __half* qr8 = qs + (warp * 16 + g + 8) * DH;
#pragma unroll
        for (int kc = 0; kc < 4; ++kc) {
            qa[kc][0] = *(const unsigned*)(qr0 + kc * 16 + 2 * tg);
            qa[kc][1] = *(const unsigned*)(qr8 + kc * 16 + 2 * tg);
            qa[kc][2] = *(const unsigned*)(qr0 + kc * 16 + 2 * tg + 8);
            qa[kc][3] = *(const unsigned*)(qr8 + kc * 16 + 2 * tg + 8);
        }
    }

    float pv[8][4];
#pragma unroll
    for (int n = 0; n < 8; ++n)
#pragma unroll
        for (int r = 0; r < 4; ++r) pv[n][r] = 0.f;
    float cl[4] = {0.f, 0.f, 0.f, 0.f};

#pragma unroll 1
    for (int jc = 0; jc < NJC; ++jc) {
        unsigned bsf[4][4][2];
        unsigned bvf[2][8][2];
#pragma unroll
        for (int nt = 0; nt < 4; ++nt) {
            const __half* kr = k1s + (jc * 32 + nt * 8 + g) * K1_STRIDE + 2 * tg;
#pragma unroll
            for (int kc = 0; kc < 4; ++kc) {
                bsf[kc][nt][0] = *(const unsigned*)(kr + kc * 16);
                bsf[kc][nt][1] = *(const unsigned*)(kr + kc * 16 + 8);
            }
        }
#pragma unroll
        for (int nt = 0; nt < 8; ++nt) {
            const __half* vr = v1t + (nt * 8 + g) * 200 + jc * 32 + 2 * tg;
#pragma unroll
            for (int kc = 0; kc < 2; ++kc) {
                bvf[kc][nt][0] = *(const unsigned*)(vr + kc * 16);
                bvf[kc][nt][1] = *(const unsigned*)(vr + kc * 16 + 8);
            }
        }

#pragma unroll 1
        for (int kk = 0; kk < KRANGE; kk += 2) {
            float sc[2][4][4];
#pragma unroll
            for (int u = 0; u < 2; ++u) {
                const __half2* k2p = k2t2 + (size_t)((kk + u) * 4 + tg) * 8;
                uint4 kr0 = *(const uint4*)(k2p);
                uint4 kr1 = *(const uint4*)(k2p + 4);
                const unsigned kh[8] = {kr0.x, kr0.y, kr0.z, kr0.w,
                                        kr1.x, kr1.y, kr1.z, kr1.w};
                unsigned aa[4][4];
#pragma unroll
                for (int kc = 0; kc < 4; ++kc) {
                    __half2 p0 = u2h2(kh[kc * 2]);
                    __half2 p1 = u2h2(kh[kc * 2 + 1]);
                    aa[kc][0] = hmul2u(qa[kc][0], p0);
                    aa[kc][1] = hmul2u(qa[kc][1], p0);
                    aa[kc][2] = hmul2u(qa[kc][2], p1);
                    aa[kc][3] = hmul2u(qa[kc][3], p1);
                }
#pragma unroll
                for (int nt = 0; nt < 4; ++nt)
#pragma unroll
                    for (int r = 0; r < 4; ++r) sc[u][nt][r] = -M_LOG2;
#pragma unroll
                for (int kc = 0; kc < 4; ++kc)
#pragma unroll
                    for (int nt = 0; nt < 4; ++nt)
                        mma16816(sc[u][nt], aa[kc][0], aa[kc][1],
                                 aa[kc][2], aa[kc][3],
                                 bsf[kc][nt][0], bsf[kc][nt][1]);
            }

            unsigned pa[2][2][4];
#pragma unroll
            for (int u = 0; u < 2; ++u)
#pragma unroll
                for (int kc = 0; kc < 2; ++kc) {
                    pa[u][kc][0] = p2exp(sc[u][2 * kc][0],     sc[u][2 * kc][1]);
                    pa[u][kc][1] = p2exp(sc[u][2 * kc][2],     sc[u][2 * kc][3]);
                    pa[u][kc][2] = p2exp(sc[u][2 * kc + 1][0], sc[u][2 * kc + 1][1]);
                    pa[u][kc][3] = p2exp(sc[u][2 * kc + 1][2], sc[u][2 * kc + 1][3]);
                }

#pragma unroll
            for (int u = 0; u < 2; ++u) {
                mma16816(cl, pa[u][0][0], pa[u][0][1], pa[u][0][2], pa[u][0][3],
                         BONES, BONES);
                mma16816(cl, pa[u][1][0], pa[u][1][1], pa[u][1][2], pa[u][1][3],
                         BONES, BONES);
            }

#pragma unroll
            for (int u = 0; u < 2; ++u) {
                const __half* v2p = v2t + (size_t)((kk + u) * 8 + g) * 8;
                uint4 vraw = *(const uint4*)(v2p);
                const unsigned vhp[4] = {vraw.x, vraw.y, vraw.z, vraw.w};
#pragma unroll
                for (int nt = 0; nt < 8; ++nt) {
                    __half2 pair = u2h2(vhp[nt >> 1]);
                    __half2 vdd  = (nt & 1) ? __high2half2(pair)
                                            : __low2half2(pair);
#pragma unroll
                    for (int kc = 0; kc < 2; ++kc) {
                        unsigned b0 = hmul2u(bvf[kc][nt][0], vdd);
                        unsigned b1 = hmul2u(bvf[kc][nt][1], vdd);
                        mma16816(pv[nt], pa[u][kc][0], pa[u][kc][1],
                                 pa[u][kc][2], pa[u][kc][3], b0, b1);
                    }
                }
            }
        }
    }

    const int row0 = bh * SEQ + i0 + warp * 16 + g;
    const int row1 = row0 + 8;
    const int p0   = split * BHD * SEQ + row0;
    const int p1   = split * BHD * SEQ + row1;
    if (tg == 0) {
        pl[p0] = cl[0];
        pl[p1] = cl[2];
    }
#pragma unroll
    for (int nt = 0; nt < 8; ++nt) {
        int d = nt * 8 + 2 * tg;
        *(float2*)(pacc + (size_t)p0 * DH + d) = make_float2(pv[nt][0], pv[nt][1]);
        *(float2*)(pacc + (size_t)p1 * DH + d) = make_float2(pv[nt][2], pv[nt][3]);
    }
}

// ---------------------------------------------------------------------------
// Combine KSPLIT partials; write attn as fp16 hi/lo at [b,n,h*64+d].
// ---------------------------------------------------------------------------
__global__ __launch_bounds__(256) void combine_kernel(
    const float* __restrict__ pacc, const float* __restrict__ pl,
    __half* __restrict__ ahi, __half* __restrict__ alo)
{
    const int row = blockIdx.x * 4 + (threadIdx.x >> 6);
    const int d   = threadIdx.x & 63;

    float den = 0.f, num = 0.f;
#pragma unroll
    for (int s = 0; s < KSPLIT; ++s) {
        int idx = s * BHD * SEQ + row;
        den += pl[idx];
        num += pacc[(size_t)idx * DH + d];
    }
    float a = num / den;

    const int bh = row / SEQ, n = row % SEQ;
    const int b = bh >> 3, h = bh & 7;
    const int o = (b * SEQ + n) * DIMM + h * DH + d;
    __half hi = __float2half_rn(a);
    ahi[o] = hi;
    alo[o] = __float2half_rn(a - __half2float(hi));
}

// ---------------------------------------------------------------------------
extern "C" void kernel_launch(void* const* d_in, const int* in_sizes, int n_in,
                              void* d_out, int out_size)
{
    (void)in_sizes; (void)n_in; (void)out_size;
    const float* tokens = (const float*)d_in[0];
    const float* w_qkv  = (const float*)d_in[1];
    const float* w_out  = (const float*)d_in[2];
    const float* qw     = (const float*)d_in[3];
    const float* k1w    = (const float*)d_in[4];
    const float* k2w    = (const float*)d_in[5];
    const float* v1w    = (const float*)d_in[6];
    const float* v2w    = (const float*)d_in[7];
    float* out = (float*)d_out;

    float *pacc, *plv;
    __half *hq, *hk1, *hk2, *hv1, *hv2;
    __half *th, *tl, *wqh, *wql, *woh, *wol, *ah, *al;
    cudaGetSymbolAddress((void**)&hq,   g_hq);
    cudaGetSymbolAddress((void**)&hk1,  g_hk1);
    cudaGetSymbolAddress((void**)&hk2,  g_hk2);
    cudaGetSymbolAddress((void**)&hv1,  g_hv1);
    cudaGetSymbolAddress((void**)&hv2,  g_hv2);
    cudaGetSymbolAddress((void**)&pacc, g_pacc);
    cudaGetSymbolAddress((void**)&plv,  g_pl);
    cudaGetSymbolAddress((void**)&th,   g_th);
    cudaGetSymbolAddress((void**)&tl,   g_tl);
    cudaGetSymbolAddress((void**)&wqh,  g_wqh);
    cudaGetSymbolAddress((void**)&wql,  g_wql);
    cudaGetSymbolAddress((void**)&woh,  g_woh);
    cudaGetSymbolAddress((void**)&wol,  g_wol);
    cudaGetSymbolAddress((void**)&ah,   g_ah);
    cudaGetSymbolAddress((void**)&al,   g_al);

    cudaFuncSetAttribute(attn_mma,
                         cudaFuncAttributeMaxDynamicSharedMemorySize,
                         ATTN_SMEM_BYTES);

    // 0) fused hi/lo splits of GEMM operands
    split3_fp16<<<(N0Q + N1Q + N2Q + 255) / 256, 256>>>(
        tokens, th, tl, w_qkv, wqh, wql, w_out, woh, wol);
    // 1) qkv GEMM + fused rmsnorm -> fp16 q/k1/k2/v1/v2 [bh, n, 64]
    gemm_qkv_rms<<<dim3(QKV_C / 64, ROWS / 64), 256>>>(
        th, tl, wqh, wql, qw, k1w, k2w, v1w, v2w, hq, hk1, hk2, hv1, hv2);
    // 2) tensor-core 2-simplicial attention, static-max split-K (6 splits)
    attn_mma<<<dim3(KSPLIT, SEQ / ITILE, BHD), NTHR, ATTN_SMEM_BYTES>>>(
        hq, hk1, hk2, hv1, hv2, pacc, plv);
    // 3) combine partials -> attn hi/lo
    combine_kernel<<<BHD * SEQ / 4, 256>>>(pacc, plv, ah, al);
    // 4) out = attn @ w_out^T : [384,512]
    gemm_nt_tch<<<dim3(DIMM / 64, ROWS / 64), 256>>>(ah, al, woh, wol, out,
                                                     ROWS, DIMM, DIMM);
}

// round 13
// speedup vs baseline: 1.0360x; 1.0360x over previous
#include <cuda_runtime.h>
#include <cuda_fp16.h>
#include <math_constants.h>
#include <cstdint>

// ---------------------------------------------------------------------------
// HigherOrderAttention — R13 (over R12):
//   * attn prologue vectorized (uint4 loads; v2 gather-pack)
//   * bsf/bvf fragment loads via ldmatrix.x4 (64 LDS.32 -> 16 LDSM per warp/jc)
//   Math identical to R12.
// ---------------------------------------------------------------------------

#define TOK_B   2
#define SEQ     192
#define DIMM    512
#define HEADS   8
#define DH      64
#define BHD     (TOK_B * HEADS)        // 16
#define QKV_C   2560
#define ROWS    (TOK_B * SEQ)          // 384
#define KSPLIT  6
#define KRANGE  (SEQ / KSPLIT)         // 32
#define ITILE   64
#define NWARP   4
#define NTHR    (NWARP * 32)           // 128
#define NJC     (SEQ / 32)             // 6

#define M_LOG2  7.2134752f             // 5 * log2(e)
#define QSCALE  0.18033688f            // 0.125 * log2(e)

// Scratch (device globals)
__device__ __half g_hq  [BHD * SEQ * DH];
__device__ __half g_hk1 [BHD * SEQ * DH];
__device__ __half g_hk2 [BHD * SEQ * DH];
__device__ __half g_hv1 [BHD * SEQ * DH];
__device__ __half g_hv2 [BHD * SEQ * DH];
__device__ float  g_pacc[KSPLIT * BHD * SEQ * DH];
__device__ float  g_pl  [KSPLIT * BHD * SEQ];
__device__ __half g_th  [ROWS * DIMM],  g_tl  [ROWS * DIMM];
__device__ __half g_wqh [QKV_C * DIMM], g_wql [QKV_C * DIMM];
__device__ __half g_woh [DIMM * DIMM],  g_wol [DIMM * DIMM];
__device__ __half g_ah  [ROWS * DIMM],  g_al  [ROWS * DIMM];

// ---------------------------------------------------------------------------
__device__ __forceinline__ void mma16816(float c[4],
                                         unsigned a0, unsigned a1,
                                         unsigned a2, unsigned a3,
                                         unsigned b0, unsigned b1)
{
    asm volatile(
        "mma.sync.aligned.m16n8k16.row.col.f32.f16.f16.f32 "
        "{%0,%1,%2,%3},{%4,%5,%6,%7},{%8,%9},{%0,%1,%2,%3};\n"
        : "+f"(c[0]), "+f"(c[1]), "+f"(c[2]), "+f"(c[3])
        : "r"(a0), "r"(a1), "r"(a2), "r"(a3), "r"(b0), "r"(b1));
}

__device__ __forceinline__ void ldsm_x4(unsigned r[4], const __half* p)
{
    unsigned sa = (unsigned)__cvta_generic_to_shared(p);
    asm volatile("ldmatrix.sync.aligned.m8n8.x4.shared.b16 {%0,%1,%2,%3}, [%4];"
                 : "=r"(r[0]), "=r"(r[1]), "=r"(r[2]), "=r"(r[3]) : "r"(sa));
}

__device__ __forceinline__ unsigned hmul2u(unsigned a, __half2 b)
{
    __half2 av = *reinterpret_cast<__half2*>(&a);
    __half2 r  = __hmul2(av, b);
    return *reinterpret_cast<unsigned*>(&r);
}

__device__ __forceinline__ __half2 u2h2(unsigned a)
{
    return *reinterpret_cast<__half2*>(&a);
}

__device__ __forceinline__ unsigned p2exp(float a, float b)
{
    __half2 h = __floats2half2_rn(a, b);
    unsigned x = *reinterpret_cast<unsigned*>(&h);
    unsigned r;
    asm("ex2.approx.f16x2 %0, %1;" : "=r"(r) : "r"(x));
    return r;
}

// ---------------------------------------------------------------------------
// Fused fp32 -> (hi,lo) fp16 split for 3 arrays.
// ---------------------------------------------------------------------------
__device__ __forceinline__ void split_quad(const float* __restrict__ x,
                                           __half* __restrict__ hi,
                                           __half* __restrict__ lo, int i)
{
    float4 v = ((const float4*)x)[i];
    __half hx = __float2half_rn(v.x), hy = __float2half_rn(v.y);
    __half hz = __float2half_rn(v.z), hw = __float2half_rn(v.w);
    ((__half2*)hi)[2 * i]     = __halves2half2(hx, hy);
    ((__half2*)hi)[2 * i + 1] = __halves2half2(hz, hw);
    ((__half2*)lo)[2 * i]     = __halves2half2(
        __float2half_rn(v.x - __half2float(hx)),
        __float2half_rn(v.y - __half2float(hy)));
    ((__half2*)lo)[2 * i + 1] = __halves2half2(
        __float2half_rn(v.z - __half2float(hz)),
        __float2half_rn(v.w - __half2float(hw)));
}

#define N0Q (ROWS * DIMM / 4)
#define N1Q (QKV_C * DIMM / 4)
#define N2Q (DIMM * DIMM / 4)

__global__ __launch_bounds__(256) void split3_fp16(
    const float* __restrict__ x0, __half* __restrict__ h0, __half* __restrict__ l0,
    const float* __restrict__ x1, __half* __restrict__ h1, __half* __restrict__ l1,
    const float* __restrict__ x2, __half* __restrict__ h2, __half* __restrict__ l2)
{
    int i = blockIdx.x * 256 + threadIdx.x;
    if (i < N0Q) {
        split_quad(x0, h0, l0, i);
    } else if (i < N0Q + N1Q) {
        split_quad(x1, h1, l1, i - N0Q);
    } else if (i < N0Q + N1Q + N2Q) {
        split_quad(x2, h2, l2, i - N0Q - N1Q);
    }
}

// ---------------------------------------------------------------------------
// Shared GEMM mainloop (64x64 tile, hi/lo fp16 operands, ldmatrix + double
// buffer). Produces per-thread c[4][4].
// ---------------------------------------------------------------------------
#define GS 40   // smem row stride in halves

struct GemmCtx {
    int wm, wn, g, tg;
};

__device__ __forceinline__ void gemm_mainloop(
    __half* smbase,                     // [2][4][64*GS]
    const __half* Ah_, const __half* Al_,
    const __half* Bh_, const __half* Bl_,
    int m0, int n0, int K, float c[4][4], GemmCtx& cx)
{
    const int t    = threadIdx.x;
    const int warp = t >> 5;
    const int lane = t & 31;
    cx.g  = lane >> 2;
    cx.tg = lane & 3;
    cx.wm = warp >> 1;
    cx.wn = warp & 1;

    const int lrow = t >> 2;
    const int lc8  = (t & 3) * 8;

    const int a_off = (cx.wm * 16 + (lane & 15)) * GS + 8 * (lane >> 4);
    const int b_row = cx.wn * 32 + (lane & 7) + ((lane >> 4) & 1) * 8;
    const int b_c8  = ((lane >> 3) & 1) * 8;

#pragma unroll
    for (int a = 0; a < 4; ++a)
#pragma unroll
        for (int b = 0; b < 4; ++b) c[a][b] = 0.f;

    const int NIT = K >> 5;
    const int BUF = 4 * 64 * GS;
    uint4 ra, rb, rc, rd;

    {
        size_t ga = (size_t)(m0 + lrow) * K + lc8;
        size_t gb = (size_t)(n0 + lrow) * K + lc8;
        ra = *(const uint4*)(Ah_ + ga);
        rb = *(const uint4*)(Al_ + ga);
        rc = *(const uint4*)(Bh_ + gb);
        rd = *(const uint4*)(Bl_ + gb);
        __half* p = smbase + lrow * GS + lc8;
        *(uint4*)(p)               = ra;
        *(uint4*)(p + 64 * GS)     = rb;
        *(uint4*)(p + 2 * 64 * GS) = rc;
        *(uint4*)(p + 3 * 64 * GS) = rd;
    }
    __syncthreads();

#pragma unroll 1
    for (int it = 0; it < NIT; ++it) {
        const int cur = it & 1;

        if (it + 1 < NIT) {
            size_t ga = (size_t)(m0 + lrow) * K + (it + 1) * 32 + lc8;
            size_t gb = (size_t)(n0 + lrow) * K + (it + 1) * 32 + lc8;
            ra = *(const uint4*)(Ah_ + ga);
            rb = *(const uint4*)(Al_ + ga);
            rc = *(const uint4*)(Bh_ + gb);
            rd = *(const uint4*)(Bl_ + gb);
        }

        const __half* Ahs = smbase + cur * BUF;
        const __half* Als = Ahs + 64 * GS;
        const __half* Bhs = Ahs + 2 * 64 * GS;
        const __half* Bls = Ahs + 3 * 64 * GS;

#pragma unroll
        for (int kc = 0; kc < 2; ++kc) {
            const int ko = kc * 16;
            unsigned ah[4], al[4];
            ldsm_x4(ah, Ahs + a_off + ko);
            ldsm_x4(al, Als + a_off + ko);
#pragma unroll
            for (int p = 0; p < 2; ++p) {
                unsigned bh[4], bl[4];
                const int bo = (b_row + p * 16) * GS + ko + b_c8;
                ldsm_x4(bh, Bhs + bo);
                ldsm_x4(bl, Bls + bo);
                mma16816(c[2 * p],     ah[0], ah[1], ah[2], ah[3], bh[0], bh[1]);
                mma16816(c[2 * p],     ah[0], ah[1], ah[2], ah[3], bl[0], bl[1]);
                mma16816(c[2 * p],     al[0], al[1], al[2], al[3], bh[0], bh[1]);
                mma16816(c[2 * p + 1], ah[0], ah[1], ah[2], ah[3], bh[2], bh[3]);
                mma16816(c[2 * p + 1], ah[0], ah[1], ah[2], ah[3], bl[2], bl[3]);
                mma16816(c[2 * p + 1], al[0], al[1], al[2], al[3], bh[2], bh[3]);
            }
        }

        if (it + 1 < NIT) {
            __half* p = smbase + (cur ^ 1) * BUF + lrow * GS + lc8;
            *(uint4*)(p)               = ra;
            *(uint4*)(p + 64 * GS)     = rb;
            *(uint4*)(p + 2 * 64 * GS) = rc;
            *(uint4*)(p + 3 * 64 * GS) = rd;
            __syncthreads();
        }
    }
}

// ---------------------------------------------------------------------------
// Plain NT GEMM (output projection): C fp32 to global.
// ---------------------------------------------------------------------------
__global__ __launch_bounds__(256) void gemm_nt_tch(
    const __half* __restrict__ Ah_, const __half* __restrict__ Al_,
    const __half* __restrict__ Bh_, const __half* __restrict__ Bl_,
    float* __restrict__ C, int M, int N, int K)
{
    __shared__ __half sm[2][4][64 * GS];
    float c[4][4];
    GemmCtx cx;
    gemm_mainloop(&sm[0][0][0], Ah_, Al_, Bh_, Bl_,
                  blockIdx.y * 64, blockIdx.x * 64, K, c, cx);

    const int row0 = blockIdx.y * 64 + cx.wm * 16 + cx.g;
    const int row1 = row0 + 8;
#pragma unroll
    for (int nt = 0; nt < 4; ++nt) {
        const int col = blockIdx.x * 64 + cx.wn * 32 + nt * 8 + 2 * cx.tg;
        *(float2*)(C + (size_t)row0 * N + col) = make_float2(c[nt][0], c[nt][1]);
        *(float2*)(C + (size_t)row1 * N + col) = make_float2(c[nt][2], c[nt][3]);
    }
}

// ---------------------------------------------------------------------------
// QKV GEMM with fused rmsnorm epilogue (identical to R12).
// ---------------------------------------------------------------------------
__global__ __launch_bounds__(256) void gemm_qkv_rms(
    const __half* __restrict__ Ah_, const __half* __restrict__ Al_,
    const __half* __restrict__ Bh_, const __half* __restrict__ Bl_,
    const float* __restrict__ qw,  const float* __restrict__ k1w,
    const float* __restrict__ k2w, const float* __restrict__ v1w,
    const float* __restrict__ v2w,
    __half* __restrict__ hq,  __half* __restrict__ hk1, __half* __restrict__ hk2,
    __half* __restrict__ hv1, __half* __restrict__ hv2)
{
    __shared__ __half sm[2][4][64 * GS];
    float c[4][4];
    GemmCtx cx;
    const int m0 = blockIdx.y * 64;
    const int n0 = blockIdx.x * 64;
    gemm_mainloop(&sm[0][0][0], Ah_, Al_, Bh_, Bl_, m0, n0, DIMM, c, cx);

    __syncthreads();
    float* smf = (float*)&sm[0][0][0];
#pragma unroll
    for (int nt = 0; nt < 4; ++nt) {
        const int col  = cx.wn * 32 + nt * 8 + 2 * cx.tg;
        const int row0 = cx.wm * 16 + cx.g;
        *(float2*)(smf + row0 * 68 + col)       = make_float2(c[nt][0], c[nt][1]);
        *(float2*)(smf + (row0 + 8) * 68 + col) = make_float2(c[nt][2], c[nt][3]);
    }
    __syncthreads();

    __half* dst;
    const float* w;
    float scale = 1.0f;
    int h;
    if (n0 < 512) {
        h = n0 >> 6;  dst = hq;  w = qw;  scale = QSCALE;
    } else if (n0 < 1536) {
        int off = n0 - 512;
        h = off >> 7;
        dst = (off & 64) ? hk2 : hk1;
        w   = (off & 64) ? k2w : k1w;
    } else {
        int off = n0 - 1536;
        h = off >> 7;
        dst = (off & 64) ? hv2 : hv1;
        w   = (off & 64) ? v2w : v1w;
    }

    const int warp = threadIdx.x >> 5;
    const int lane = threadIdx.x & 31;
    const float w0 = w[lane];
    const float w1 = w[lane + 32];

#pragma unroll
    for (int rr = 0; rr < 8; ++rr) {
        const int r    = warp * 8 + rr;
        const int grow = m0 + r;
        const int b    = grow / SEQ;
        const int n    = grow % SEQ;

        float x0 = smf[r * 68 + lane];
        float x1 = smf[r * 68 + lane + 32];
        float ss = x0 * x0 + x1 * x1;
#pragma unroll
        for (int o = 16; o >= 1; o >>= 1)
            ss += __shfl_xor_sync(0xffffffffu, ss, o);
        float inv = rsqrtf(ss * (1.0f / 64.0f) + 1.1920929e-07f) * scale;

        __half* yp = dst + ((size_t)(b * HEADS + h) * SEQ + n) * DH;
        yp[lane]      = __float2half(x0 * inv * w0);
        yp[lane + 32] = __float2half(x1 * inv * w1);
    }
}

// ---------------------------------------------------------------------------
// Tensor-core attention (R12 math; vectorized prologue + ldmatrix fragments).
// ---------------------------------------------------------------------------
#define K1_STRIDE 72
#define SM_K1   (SEQ * K1_STRIDE)
#define SM_V1T  (DH * 200)
#define SM_Q    (ITILE * DH)
#define SM_K2   (KRANGE * DH)
#define SM_V2   (KRANGE * DH)
#define ATTN_SMEM_HALVES (SM_K1 + SM_V1T + SM_Q + SM_K2 + SM_V2)
#define ATTN_SMEM_BYTES  (ATTN_SMEM_HALVES * 2)

__global__ __launch_bounds__(NTHR, 2) void attn_mma(
    const __half* __restrict__ hq,  const __half* __restrict__ hk1,
    const __half* __restrict__ hk2, const __half* __restrict__ hv1,
    const __half* __restrict__ hv2,
    float* __restrict__ pacc, float* __restrict__ pl)
{
    extern __shared__ __align__(16) __half smh[];
    __half*  k1s  = smh;
    __half*  v1t  = k1s + SM_K1;
    __half*  qs   = v1t + SM_V1T;
    __half2* k2t2 = (__half2*)(qs + SM_Q);
    __half*  v2t  = qs + SM_Q + SM_K2;

    const int split = blockIdx.x;
    const int i0    = blockIdx.y * ITILE;
    const int bh    = blockIdx.z;
    const int t     = threadIdx.x;
    const int kbeg  = split * KRANGE;

    const __half* k1b = hk1 + bh * SEQ * DH;
    const __half* v1b = hv1 + bh * SEQ * DH;
    const __half* k2b = hk2 + (bh * SEQ + kbeg) * DH;
    const __half* v2b = hv2 + (bh * SEQ + kbeg) * DH;
    const __half* qb  = hq  + (bh * SEQ + i0) * DH;

    // ---- vectorized prologue ----------------------------------------------
    // k1 copy + v1 transpose: one uint4 per 8 elements
    for (int e = t; e < SEQ * DH / 8; e += NTHR) {
        int j = e >> 3, c8 = (e & 7) * 8;
        *(uint4*)(k1s + j * K1_STRIDE + c8) = *(const uint4*)(k1b + j * DH + c8);
        uint4 vv = *(const uint4*)(v1b + j * DH + c8);
        const __half* vh = (const __half*)&vv;
#pragma unroll
        for (int m = 0; m < 8; ++m)
            v1t[(c8 + m) * 200 + j] = vh[m];
    }
    // q copy
    for (int e = t; e < ITILE * DH / 8; e += NTHR)
        ((uint4*)qs)[e] = ((const uint4*)qb)[e];
    // k2 relayout (half2 gather, as before)
    for (int e = t; e < KRANGE * 32; e += NTHR) {
        int kk = e >> 5, r = e & 31;
        int tg_ = r >> 3, s = r & 7;
        int col = (s >> 1) * 16 + (s & 1) * 8 + tg_ * 2;
        k2t2[e] = *(const __half2*)(k2b + kk * DH + col);
    }
    // v2 relayout: gather 8, store uint4
    for (int e = t; e < KRANGE * 8; e += NTHR) {
        int kk = e >> 3, g_ = e & 7;
        __half tmp[8];
#pragma unroll
        for (int nt = 0; nt < 8; ++nt)
            tmp[nt] = v2b[kk * DH + nt * 8 + g_];
        *(uint4*)(v2t + e * 8) = *(const uint4*)tmp;
    }
    __syncthreads();

    const int warp = t >> 5;
    const int lane = t & 31;
    const int g    = lane >> 2;
    const int tg   = lane & 3;

    // ldmatrix lane mapping (same convention as validated GEMM b-frags)
    const int l7   = lane & 7;
    const int c8b  = ((lane >> 3) & 1) * 8;
    const int ntp  = (lane >> 4) & 1;

    const unsigned BONES = 0x3C003C00u;

    unsigned qa[4][4];
    {
        const __half* qr0 = qs + (warp * 16 + g) * DH;
        const __half* qr8 = qs + (warp * 16 + g + 8) * DH;
#pragma unroll
        for (int kc = 0; kc < 4; ++kc) {
            qa[kc][0] = *(const unsigned*)(qr0 + kc * 16 + 2 * tg);
            qa[kc][1] = *(const unsigned*)(qr8 + kc * 16 + 2 * tg);
            qa[kc][2] = *(const unsigned*)(qr0 + kc * 16 + 2 * tg + 8);
            qa[kc][3] = *(const unsigned*)(qr8 + kc * 16 + 2 * tg + 8);
        }
    }

    float pv[8][4];
#pragma unroll
    for (int n = 0; n < 8; ++n)
#pragma unroll
        for (int r = 0; r < 4; ++r) pv[n][r] = 0.f;
    float cl[4] = {0.f, 0.f, 0.f, 0.f};

#pragma unroll 1
    for (int jc = 0; jc < NJC; ++jc) {
        // ---- k-invariant fragments via ldmatrix.x4 -------------------------
        unsigned bsf[4][4][2];   // [kc][nt][b01]
        unsigned bvf[2][8][2];
#pragma unroll
        for (int kc = 0; kc < 4; ++kc)
#pragma unroll
            for (int np = 0; np < 2; ++np) {
                unsigned r4[4];
                const __half* p = k1s
                    + (jc * 32 + (np * 2 + ntp) * 8 + l7) * K1_STRIDE
                    + kc * 16 + c8b;
                ldsm_x4(r4, p);
                bsf[kc][2 * np][0]     = r4[0];
                bsf[kc][2 * np][1]     = r4[1];
                bsf[kc][2 * np + 1][0] = r4[2];
                bsf[kc][2 * np + 1][1] = r4[3];
            }
#pragma unroll
        for (int kc = 0; kc < 2; ++kc)
#pragma unroll
            for (int np = 0; np < 4; ++np) {
                unsigned r4[4];
                const __half* p = v1t
                    + ((np * 2 + ntp) * 8 + l7) * 200
                    + jc * 32 + kc * 16 + c8b;
                ldsm_x4(r4, p);
                bvf[kc][2 * np][0]     = r4[0];
                bvf[kc][2 * np][1]     = r4[1];
                bvf[kc][2 * np + 1][0] = r4[2];
                bvf[kc][2 * np + 1][1] = r4[3];
            }

#pragma unroll 1
        for (int kk = 0; kk < KRANGE; kk += 2) {
            float sc[2][4][4];
#pragma unroll
            for (int u = 0; u < 2; ++u) {
                const __half2* k2p = k2t2 + (size_t)((kk + u) * 4 + tg) * 8;
                uint4 kr0 = *(const uint4*)(k2p);
                uint4 kr1 = *(const uint4*)(k2p + 4);
                const unsigned kh[8] = {kr0.x, kr0.y, kr0.z, kr0.w,
                                        kr1.x, kr1.y, kr1.z, kr1.w};
                unsigned aa[4][4];
#pragma unroll
                for (int kc = 0; kc < 4; ++kc) {
                    __half2 p0 = u2h2(kh[kc * 2]);
                    __half2 p1 = u2h2(kh[kc * 2 + 1]);
                    aa[kc][0] = hmul2u(qa[kc][0], p0);
                    aa[kc][1] = hmul2u(qa[kc][1], p0);
                    aa[kc][2] = hmul2u(qa[kc][2], p1);
                    aa[kc][3] = hmul2u(qa[kc][3], p1);
                }
#pragma unroll
                for (int nt = 0; nt < 4; ++nt)
#pragma unroll
                    for (int r = 0; r < 4; ++r) sc[u][nt][r] = -M_LOG2;
#pragma unroll
                for (int kc = 0; kc < 4; ++kc)
#pragma unroll
                    for (int nt = 0; nt < 4; ++nt)
                        mma16816(sc[u][nt], aa[kc][0], aa[kc][1],
                                 aa[kc][2], aa[kc][3],
                                 bsf[kc][nt][0], bsf[kc][nt][1]);
            }

            unsigned pa[2][2][4];
#pragma unroll
            for (int u = 0; u < 2; ++u)
#pragma unroll
                for (int kc = 0; kc < 2; ++kc) {
                    pa[u][kc][0] = p2exp(sc[u][2 * kc][0],     sc[u][2 * kc][1]);
                    pa[u][kc][1] = p2exp(sc[u][2 * kc][2],     sc[u][2 * kc][3]);
                    pa[u][kc][2] = p2exp(sc[u][2 * kc + 1][0], sc[u][2 * kc + 1][1]);
                    pa[u][kc][3] = p2exp(sc[u][2 * kc + 1][2], sc[u][2 * kc + 1][3]);
                }

#pragma unroll
            for (int u = 0; u < 2; ++u) {
                mma16816(cl, pa[u][0][0], pa[u][0][1], pa[u][0][2], pa[u][0][3],
                         BONES, BONES);
                mma16816(cl, pa[u][1][0], pa[u][1][1], pa[u][1][2], pa[u][1][3],
                         BONES, BONES);
            }

#pragma unroll
            for (int u = 0; u < 2; ++u) {
                const __half* v2p = v2t + (size_t)((kk + u) * 8 + g) * 8;
                uint4 vraw = *(const uint4*)(v2p);
                const unsigned vhp[4] = {vraw.x, vraw.y, vraw.z, vraw.w};
#pragma unroll
                for (int nt = 0; nt < 8; ++nt) {
                    __half2 pair = u2h2(vhp[nt >> 1]);
                    __half2 vdd  = (nt & 1) ? __high2half2(pair)
                                            : __low2half2(pair);
#pragma unroll
                    for (int kc = 0; kc < 2; ++kc) {
                        unsigned b0 = hmul2u(bvf[kc][nt][0], vdd);
                        unsigned b1 = hmul2u(bvf[kc][nt][1], vdd);
                        mma16816(pv[nt], pa[u][kc][0], pa[u][kc][1],
                                 pa[u][kc][2], pa[u][kc][3], b0, b1);
                    }
                }
            }
        }
    }

    const int row0 = bh * SEQ + i0 + warp * 16 + g;
    const int row1 = row0 + 8;
    const int p0   = split * BHD * SEQ + row0;
    const int p1   = split * BHD * SEQ + row1;
    if (tg == 0) {
        pl[p0] = cl[0];
        pl[p1] = cl[2];
    }
#pragma unroll
    for (int nt = 0; nt < 8; ++nt) {
        int d = nt * 8 + 2 * tg;
        *(float2*)(pacc + (size_t)p0 * DH + d) = make_float2(pv[nt][0], pv[nt][1]);
        *(float2*)(pacc + (size_t)p1 * DH + d) = make_float2(pv[nt][2], pv[nt][3]);
    }
}

// ---------------------------------------------------------------------------
// Combine KSPLIT partials; write attn as fp16 hi/lo at [b,n,h*64+d].
// ---------------------------------------------------------------------------
__global__ __launch_bounds__(256) void combine_kernel(
    const float* __restrict__ pacc, const float* __restrict__ pl,
    __half* __restrict__ ahi, __half* __restrict__ alo)
{
    const int row = blockIdx.x * 4 + (threadIdx.x >> 6);
    const int d   = threadIdx.x & 63;

    float den = 0.f, num = 0.f;
#pragma unroll
    for (int s = 0; s < KSPLIT; ++s) {
        int idx = s * BHD * SEQ + row;
        den += pl[idx];
        num += pacc[(size_t)idx * DH + d];
    }
    float a = num / den;

    const int bh = row / SEQ, n = row % SEQ;
    const int b = bh >> 3, h = bh & 7;
    const int o = (b * SEQ + n) * DIMM + h * DH + d;
    __half hi = __float2half_rn(a);
    ahi[o] = hi;
    alo[o] = __float2half_rn(a - __half2float(hi));
}

// ---------------------------------------------------------------------------
extern "C" void kernel_launch(void* const* d_in, const int* in_sizes, int n_in,
                              void* d_out, int out_size)
{
    (void)in_sizes; (void)n_in; (void)out_size;
    const float* tokens = (const float*)d_in[0];
    const float* w_qkv  = (const float*)d_in[1];
    const float* w_out  = (const float*)d_in[2];
    const float* qw     = (const float*)d_in[3];
    const float* k1w    = (const float*)d_in[4];
    const float* k2w    = (const float*)d_in[5];
    const float* v1w    = (const float*)d_in[6];
    const float* v2w    = (const float*)d_in[7];
    float* out = (float*)d_out;

    float *pacc, *plv;
    __half *hq, *hk1, *hk2, *hv1, *hv2;
    __half *th, *tl, *wqh, *wql, *woh, *wol, *ah, *al;
    cudaGetSymbolAddress((void**)&hq,   g_hq);
    cudaGetSymbolAddress((void**)&hk1,  g_hk1);
    cudaGetSymbolAddress((void**)&hk2,  g_hk2);
    cudaGetSymbolAddress((void**)&hv1,  g_hv1);
    cudaGetSymbolAddress((void**)&hv2,  g_hv2);
    cudaGetSymbolAddress((void**)&pacc, g_pacc);
    cudaGetSymbolAddress((void**)&plv,  g_pl);
    cudaGetSymbolAddress((void**)&th,   g_th);
    cudaGetSymbolAddress((void**)&tl,   g_tl);
    cudaGetSymbolAddress((void**)&wqh,  g_wqh);
    cudaGetSymbolAddress((void**)&wql,  g_wql);
    cudaGetSymbolAddress((void**)&woh,  g_woh);
    cudaGetSymbolAddress((void**)&wol,  g_wol);
    cudaGetSymbolAddress((void**)&ah,   g_ah);
    cudaGetSymbolAddress((void**)&al,   g_al);

    cudaFuncSetAttribute(attn_mma,
                         cudaFuncAttributeMaxDynamicSharedMemorySize,
                         ATTN_SMEM_BYTES);

    // 0) fused hi/lo splits of GEMM operands
    split3_fp16<<<(N0Q + N1Q + N2Q + 255) / 256, 256>>>(
        tokens, th, tl, w_qkv, wqh, wql, w_out, woh, wol);
    // 1) qkv GEMM + fused rmsnorm -> fp16 q/k1/k2/v1/v2 [bh, n, 64]
    gemm_qkv_rms<<<dim3(QKV_C / 64, ROWS / 64), 256>>>(
        th, tl, wqh, wql, qw, k1w, k2w, v1w, v2w, hq, hk1, hk2, hv1, hv2);
    // 2) tensor-core 2-simplicial attention, static-max split-K (6 splits)
    attn_mma<<<dim3(KSPLIT, SEQ / ITILE, BHD), NTHR, ATTN_SMEM_BYTES>>>(
        hq, hk1, hk2, hv1, hv2, pacc, plv);
    // 3) combine partials -> attn hi/lo
    combine_kernel<<<BHD * SEQ / 4, 256>>>(pacc, plv, ah, al);
    // 4) out = attn @ w_out^T : [384,512]
    gemm_nt_tch<<<dim3(DIMM / 64, ROWS / 64), 256>>>(ah, al, woh, wol, out,
                                                     ROWS, DIMM, DIMM);
}

// round 14
// speedup vs baseline: 1.0482x; 1.0118x over previous
#include <cuda_runtime.h>
#include <cuda_fp16.h>
#include <math_constants.h>
#include <cstdint>

// ---------------------------------------------------------------------------
// HigherOrderAttention — R14 (over R13):
//   * l-sum moved OFF the tensor pipe: ones-mmas (2/34 per step) replaced by
//     HADD2 tree + fp32 accumulation + epilogue quad-shuffle reduce.
//   Everything else identical to R13.
// ---------------------------------------------------------------------------

#define TOK_B   2
#define SEQ     192
#define DIMM    512
#define HEADS   8
#define DH      64
#define BHD     (TOK_B * HEADS)        // 16
#define QKV_C   2560
#define ROWS    (TOK_B * SEQ)          // 384
#define KSPLIT  6
#define KRANGE  (SEQ / KSPLIT)         // 32
#define ITILE   64
#define NWARP   4
#define NTHR    (NWARP * 32)           // 128
#define NJC     (SEQ / 32)             // 6

#define M_LOG2  7.2134752f             // 5 * log2(e)
#define QSCALE  0.18033688f            // 0.125 * log2(e)

// Scratch (device globals)
__device__ __half g_hq  [BHD * SEQ * DH];
__device__ __half g_hk1 [BHD * SEQ * DH];
__device__ __half g_hk2 [BHD * SEQ * DH];
__device__ __half g_hv1 [BHD * SEQ * DH];
__device__ __half g_hv2 [BHD * SEQ * DH];
__device__ float  g_pacc[KSPLIT * BHD * SEQ * DH];
__device__ float  g_pl  [KSPLIT * BHD * SEQ];
__device__ __half g_th  [ROWS * DIMM],  g_tl  [ROWS * DIMM];
__device__ __half g_wqh [QKV_C * DIMM], g_wql [QKV_C * DIMM];
__device__ __half g_woh [DIMM * DIMM],  g_wol [DIMM * DIMM];
__device__ __half g_ah  [ROWS * DIMM],  g_al  [ROWS * DIMM];

// ---------------------------------------------------------------------------
__device__ __forceinline__ void mma16816(float c[4],
                                         unsigned a0, unsigned a1,
                                         unsigned a2, unsigned a3,
                                         unsigned b0, unsigned b1)
{
    asm volatile(
        "mma.sync.aligned.m16n8k16.row.col.f32.f16.f16.f32 "
        "{%0,%1,%2,%3},{%4,%5,%6,%7},{%8,%9},{%0,%1,%2,%3};\n"
        : "+f"(c[0]), "+f"(c[1]), "+f"(c[2]), "+f"(c[3])
        : "r"(a0), "r"(a1), "r"(a2), "r"(a3), "r"(b0), "r"(b1));
}

__device__ __forceinline__ void ldsm_x4(unsigned r[4], const __half* p)
{
    unsigned sa = (unsigned)__cvta_generic_to_shared(p);
    asm volatile("ldmatrix.sync.aligned.m8n8.x4.shared.b16 {%0,%1,%2,%3}, [%4];"
                 : "=r"(r[0]), "=r"(r[1]), "=r"(r[2]), "=r"(r[3]) : "r"(sa));
}

__device__ __forceinline__ unsigned hmul2u(unsigned a, __half2 b)
{
    __half2 av = *reinterpret_cast<__half2*>(&a);
    __half2 r  = __hmul2(av, b);
    return *reinterpret_cast<unsigned*>(&r);
}

__device__ __forceinline__ __half2 u2h2(unsigned a)
{
    return *reinterpret_cast<__half2*>(&a);
}

__device__ __forceinline__ unsigned p2exp(float a, float b)
{
    __half2 h = __floats2half2_rn(a, b);
    unsigned x = *reinterpret_cast<unsigned*>(&h);
    unsigned r;
    asm("ex2.approx.f16x2 %0, %1;" : "=r"(r) : "r"(x));
    return r;
}

// ---------------------------------------------------------------------------
// Fused fp32 -> (hi,lo) fp16 split for 3 arrays.
// ---------------------------------------------------------------------------
__device__ __forceinline__ void split_quad(const float* __restrict__ x,
                                           __half* __restrict__ hi,
                                           __half* __restrict__ lo, int i)
{
    float4 v = ((const float4*)x)[i];
    __half hx = __float2half_rn(v.x), hy = __float2half_rn(v.y);
    __half hz = __float2half_rn(v.z), hw = __float2half_rn(v.w);
    ((__half2*)hi)[2 * i]     = __halves2half2(hx, hy);
    ((__half2*)hi)[2 * i + 1] = __halves2half2(hz, hw);
    ((__half2*)lo)[2 * i]     = __halves2half2(
        __float2half_rn(v.x - __half2float(hx)),
        __float2half_rn(v.y - __half2float(hy)));
    ((__half2*)lo)[2 * i + 1] = __halves2half2(
        __float2half_rn(v.z - __half2float(hz)),
        __float2half_rn(v.w - __half2float(hw)));
}

#define N0Q (ROWS * DIMM / 4)
#define N1Q (QKV_C * DIMM / 4)
#define N2Q (DIMM * DIMM / 4)

__global__ __launch_bounds__(256) void split3_fp16(
    const float* __restrict__ x0, __half* __restrict__ h0, __half* __restrict__ l0,
    const float* __restrict__ x1, __half* __restrict__ h1, __half* __restrict__ l1,
    const float* __restrict__ x2, __half* __restrict__ h2, __half* __restrict__ l2)
{
    int i = blockIdx.x * 256 + threadIdx.x;
    if (i < N0Q) {
        split_quad(x0, h0, l0, i);
    } else if (i < N0Q + N1Q) {
        split_quad(x1, h1, l1, i - N0Q);
    } else if (i < N0Q + N1Q + N2Q) {
        split_quad(x2, h2, l2, i - N0Q - N1Q);
    }
}

// ---------------------------------------------------------------------------
// Shared GEMM mainloop (64x64 tile, hi/lo fp16 operands, ldmatrix + double
// buffer). Produces per-thread c[4][4].
// ---------------------------------------------------------------------------
#define GS 40   // smem row stride in halves

struct GemmCtx {
    int wm, wn, g, tg;
};

__device__ __forceinline__ void gemm_mainloop(
    __half* smbase,                     // [2][4][64*GS]
    const __half* Ah_, const __half* Al_,
    const __half* Bh_, const __half* Bl_,
    int m0, int n0, int K, float c[4][4], GemmCtx& cx)
{
    const int t    = threadIdx.x;
    const int warp = t >> 5;
    const int lane = t & 31;
    cx.g  = lane >> 2;
    cx.tg = lane & 3;
    cx.wm = warp >> 1;
    cx.wn = warp & 1;

    const int lrow = t >> 2;
    const int lc8  = (t & 3) * 8;

    const int a_off = (cx.wm * 16 + (lane & 15)) * GS + 8 * (lane >> 4);
    const int b_row = cx.wn * 32 + (lane & 7) + ((lane >> 4) & 1) * 8;
    const int b_c8  = ((lane >> 3) & 1) * 8;

#pragma unroll
    for (int a = 0; a < 4; ++a)
#pragma unroll
        for (int b = 0; b < 4; ++b) c[a][b] = 0.f;

    const int NIT = K >> 5;
    const int BUF = 4 * 64 * GS;
    uint4 ra, rb, rc, rd;

    {
        size_t ga = (size_t)(m0 + lrow) * K + lc8;
        size_t gb = (size_t)(n0 + lrow) * K + lc8;
        ra = *(const uint4*)(Ah_ + ga);
        rb = *(const uint4*)(Al_ + ga);
        rc = *(const uint4*)(Bh_ + gb);
        rd = *(const uint4*)(Bl_ + gb);
        __half* p = smbase + lrow * GS + lc8;
        *(uint4*)(p)               = ra;
        *(uint4*)(p + 64 * GS)     = rb;
        *(uint4*)(p + 2 * 64 * GS) = rc;
        *(uint4*)(p + 3 * 64 * GS) = rd;
    }
    __syncthreads();

#pragma unroll 1
    for (int it = 0; it < NIT; ++it) {
        const int cur = it & 1;

        if (it + 1 < NIT) {
            size_t ga = (size_t)(m0 + lrow) * K + (it + 1) * 32 + lc8;
            size_t gb = (size_t)(n0 + lrow) * K + (it + 1) * 32 + lc8;
            ra = *(const uint4*)(Ah_ + ga);
            rb = *(const uint4*)(Al_ + ga);
            rc = *(const uint4*)(Bh_ + gb);
            rd = *(const uint4*)(Bl_ + gb);
        }

        const __half* Ahs = smbase + cur * BUF;
        const __half* Als = Ahs + 64 * GS;
        const __half* Bhs = Ahs + 2 * 64 * GS;
        const __half* Bls = Ahs + 3 * 64 * GS;

#pragma unroll
        for (int kc = 0; kc < 2; ++kc) {
            const int ko = kc * 16;
            unsigned ah[4], al[4];
            ldsm_x4(ah, Ahs + a_off + ko);
            ldsm_x4(al, Als + a_off + ko);
#pragma unroll
            for (int p = 0; p < 2; ++p) {
                unsigned bh[4], bl[4];
                const int bo = (b_row + p * 16) * GS + ko + b_c8;
                ldsm_x4(bh, Bhs + bo);
                ldsm_x4(bl, Bls + bo);
                mma16816(c[2 * p],     ah[0], ah[1], ah[2], ah[3], bh[0], bh[1]);
                mma16816(c[2 * p],     ah[0], ah[1], ah[2], ah[3], bl[0], bl[1]);
                mma16816(c[2 * p],     al[0], al[1], al[2], al[3], bh[0], bh[1]);
                mma16816(c[2 * p + 1], ah[0], ah[1], ah[2], ah[3], bh[2], bh[3]);
                mma16816(c[2 * p + 1], ah[0], ah[1], ah[2], ah[3], bl[2], bl[3]);
                mma16816(c[2 * p + 1], al[0], al[1], al[2], al[3], bh[2], bh[3]);
            }
        }

        if (it + 1 < NIT) {
            __half* p = smbase + (cur ^ 1) * BUF + lrow * GS + lc8;
            *(uint4*)(p)               = ra;
            *(uint4*)(p + 64 * GS)     = rb;
            *(uint4*)(p + 2 * 64 * GS) = rc;
            *(uint4*)(p + 3 * 64 * GS) = rd;
            __syncthreads();
        }
    }
}

// ---------------------------------------------------------------------------
// Plain NT GEMM (output projection): C fp32 to global.
// ---------------------------------------------------------------------------
__global__ __launch_bounds__(256) void gemm_nt_tch(
    const __half* __restrict__ Ah_, const __half* __restrict__ Al_,
    const __half* __restrict__ Bh_, const __half* __restrict__ Bl_,
    float* __restrict__ C, int M, int N, int K)
{
    __shared__ __half sm[2][4][64 * GS];
    float c[4][4];
    GemmCtx cx;
    gemm_mainloop(&sm[0][0][0], Ah_, Al_, Bh_, Bl_,
                  blockIdx.y * 64, blockIdx.x * 64, K, c, cx);

    const int row0 = blockIdx.y * 64 + cx.wm * 16 + cx.g;
    const int row1 = row0 + 8;
#pragma unroll
    for (int nt = 0; nt < 4; ++nt) {
        const int col = blockIdx.x * 64 + cx.wn * 32 + nt * 8 + 2 * cx.tg;
        *(float2*)(C + (size_t)row0 * N + col) = make_float2(c[nt][0], c[nt][1]);
        *(float2*)(C + (size_t)row1 * N + col) = make_float2(c[nt][2], c[nt][3]);
    }
}

// ---------------------------------------------------------------------------
// QKV GEMM with fused rmsnorm epilogue (identical to R13).
// ---------------------------------------------------------------------------
__global__ __launch_bounds__(256) void gemm_qkv_rms(
    const __half* __restrict__ Ah_, const __half* __restrict__ Al_,
    const __half* __restrict__ Bh_, const __half* __restrict__ Bl_,
    const float* __restrict__ qw,  const float* __restrict__ k1w,
    const float* __restrict__ k2w, const float* __restrict__ v1w,
    const float* __restrict__ v2w,
    __half* __restrict__ hq,  __half* __restrict__ hk1, __half* __restrict__ hk2,
    __half* __restrict__ hv1, __half* __restrict__ hv2)
{
    __shared__ __half sm[2][4][64 * GS];
    float c[4][4];
    GemmCtx cx;
    const int m0 = blockIdx.y * 64;
    const int n0 = blockIdx.x * 64;
    gemm_mainloop(&sm[0][0][0], Ah_, Al_, Bh_, Bl_, m0, n0, DIMM, c, cx);

    __syncthreads();
    float* smf = (float*)&sm[0][0][0];
#pragma unroll
    for (int nt = 0; nt < 4; ++nt) {
        const int col  = cx.wn * 32 + nt * 8 + 2 * cx.tg;
        const int row0 = cx.wm * 16 + cx.g;
        *(float2*)(smf + row0 * 68 + col)       = make_float2(c[nt][0], c[nt][1]);
        *(float2*)(smf + (row0 + 8) * 68 + col) = make_float2(c[nt][2], c[nt][3]);
    }
    __syncthreads();

    __half* dst;
    const float* w;
    float scale = 1.0f;
    int h;
    if (n0 < 512) {
        h = n0 >> 6;  dst = hq;  w = qw;  scale = QSCALE;
    } else if (n0 < 1536) {
        int off = n0 - 512;
        h = off >> 7;
        dst = (off & 64) ? hk2 : hk1;
        w   = (off & 64) ? k2w : k1w;
    } else {
        int off = n0 - 1536;
        h = off >> 7;
        dst = (off & 64) ? hv2 : hv1;
        w   = (off & 64) ? v2w : v1w;
    }

    const int warp = threadIdx.x >> 5;
    const int lane = threadIdx.x & 31;
    const float w0 = w[lane];
    const float w1 = w[lane + 32];

#pragma unroll
    for (int rr = 0; rr < 8; ++rr) {
        const int r    = warp * 8 + rr;
        const int grow = m0 + r;
        const int b    = grow / SEQ;
        const int n    = grow % SEQ;

        float x0 = smf[r * 68 + lane];
        float x1 = smf[r * 68 + lane + 32];
        float ss = x0 * x0 + x1 * x1;
#pragma unroll
        for (int o = 16; o >= 1; o >>= 1)
            ss += __shfl_xor_sync(0xffffffffu, ss, o);
        float inv = rsqrtf(ss * (1.0f / 64.0f) + 1.1920929e-07f) * scale;

        __half* yp = dst + ((size_t)(b * HEADS + h) * SEQ + n) * DH;
        yp[lane]      = __float2half(x0 * inv * w0);
        yp[lane + 32] = __float2half(x1 * inv * w1);
    }
}

// ---------------------------------------------------------------------------
// Tensor-core attention (R13 + l-sum moved off tensor pipe).
// ---------------------------------------------------------------------------
#define K1_STRIDE 72
#define SM_K1   (SEQ * K1_STRIDE)
#define SM_V1T  (DH * 200)
#define SM_Q    (ITILE * DH)
#define SM_K2   (KRANGE * DH)
#define SM_V2   (KRANGE * DH)
#define ATTN_SMEM_HALVES (SM_K1 + SM_V1T + SM_Q + SM_K2 + SM_V2)
#define ATTN_SMEM_BYTES  (ATTN_SMEM_HALVES * 2)

__global__ __launch_bounds__(NTHR, 2) void attn_mma(
    const __half* __restrict__ hq,  const __half* __restrict__ hk1,
    const __half* __restrict__ hk2, const __half* __restrict__ hv1,
    const __half* __restrict__ hv2,
    float* __restrict__ pacc, float* __restrict__ pl)
{
    extern __shared__ __align__(16) __half smh[];
    __half*  k1s  = smh;
    __half*  v1t  = k1s + SM_K1;
    __half*  qs   = v1t + SM_V1T;
    __half2* k2t2 = (__half2*)(qs + SM_Q);
    __half*  v2t  = qs + SM_Q + SM_K2;

    const int split = blockIdx.x;
    const int i0    = blockIdx.y * ITILE;
    const int bh    = blockIdx.z;
    const int t     = threadIdx.x;
    const int kbeg  = split * KRANGE;

    const __half* k1b = hk1 + bh * SEQ * DH;
    const __half* v1b = hv1 + bh * SEQ * DH;
    const __half* k2b = hk2 + (bh * SEQ + kbeg) * DH;
    const __half* v2b = hv2 + (bh * SEQ + kbeg) * DH;
    const __half* qb  = hq  + (bh * SEQ + i0) * DH;

    // ---- vectorized prologue ----------------------------------------------
    for (int e = t; e < SEQ * DH / 8; e += NTHR) {
        int j = e >> 3, c8 = (e & 7) * 8;
        *(uint4*)(k1s + j * K1_STRIDE + c8) = *(const uint4*)(k1b + j * DH + c8);
        uint4 vv = *(const uint4*)(v1b + j * DH + c8);
        const __half* vh = (const __half*)&vv;
#pragma unroll
        for (int m = 0; m < 8; ++m)
            v1t[(c8 + m) * 200 + j] = vh[m];
    }
    for (int e = t; e < ITILE * DH / 8; e += NTHR)
        ((uint4*)qs)[e] = ((const uint4*)qb)[e];
    for (int e = t; e < KRANGE * 32; e += NTHR) {
        int kk = e >> 5, r = e & 31;
        int tg_ = r >> 3, s = r & 7;
        int col = (s >> 1) * 16 + (s & 1) * 8 + tg_ * 2;
        k2t2[e] = *(const __half2*)(k2b + kk * DH + col);
    }
    for (int e = t; e < KRANGE * 8; e += NTHR) {
        int kk = e >> 3, g_ = e & 7;
        __half tmp[8];
#pragma unroll
        for (int nt = 0; nt < 8; ++nt)
            tmp[nt] = v2b[kk * DH + nt * 8 + g_];
        *(uint4*)(v2t + e * 8) = *(const uint4*)tmp;
    }
    __syncthreads();

    const int warp = t >> 5;
    const int lane = t & 31;
    const int g    = lane >> 2;
    const int tg   = lane & 3;

    const int l7   = lane & 7;
    const int c8b  = ((lane >> 3) & 1) * 8;
    const int ntp  = (lane >> 4) & 1;

    unsigned qa[4][4];
    {
        const __half* qr0 = qs + (warp * 16 + g) * DH;
        const __half* qr8 = qs + (warp * 16 + g + 8) * DH;
#pragma unroll
        for (int kc = 0; kc < 4; ++kc) {
            qa[kc][0] = *(const unsigned*)(qr0 + kc * 16 + 2 * tg);
            qa[kc][1] = *(const unsigned*)(qr8 + kc * 16 + 2 * tg);
            qa[kc][2] = *(const unsigned*)(qr0 + kc * 16 + 2 * tg + 8);
            qa[kc][3] = *(const unsigned*)(qr8 + kc * 16 + 2 * tg + 8);
        }
    }

    float pv[8][4];
#pragma unroll
    for (int n = 0; n < 8; ++n)
#pragma unroll
        for (int r = 0; r < 4; ++r) pv[n][r] = 0.f;
    float l0 = 0.f, l1 = 0.f;   // fp32 l accumulators (rows g, g+8)

#pragma unroll 1
    for (int jc = 0; jc < NJC; ++jc) {
        unsigned bsf[4][4][2];
        unsigned bvf[2][8][2];
#pragma unroll
        for (int kc = 0; kc < 4; ++kc)
#pragma unroll
            for (int np = 0; np < 2; ++np) {
                unsigned r4[4];
                const __half* p = k1s
                    + (jc * 32 + (np * 2 + ntp) * 8 + l7) * K1_STRIDE
                    + kc * 16 + c8b;
                ldsm_x4(r4, p);
                bsf[kc][2 * np][0]     = r4[0];
                bsf[kc][2 * np][1]     = r4[1];
                bsf[kc][2 * np + 1][0] = r4[2];
                bsf[kc][2 * np + 1][1] = r4[3];
            }
#pragma unroll
        for (int kc = 0; kc < 2; ++kc)
#pragma unroll
            for (int np = 0; np < 4; ++np) {
                unsigned r4[4];
                const __half* p = v1t
                    + ((np * 2 + ntp) * 8 + l7) * 200
                    + jc * 32 + kc * 16 + c8b;
                ldsm_x4(r4, p);
                bvf[kc][2 * np][0]     = r4[0];
                bvf[kc][2 * np][1]     = r4[1];
                bvf[kc][2 * np + 1][0] = r4[2];
                bvf[kc][2 * np + 1][1] = r4[3];
            }

#pragma unroll 1
        for (int kk = 0; kk < KRANGE; kk += 2) {
            float sc[2][4][4];
#pragma unroll
            for (int u = 0; u < 2; ++u) {
                const __half2* k2p = k2t2 + (size_t)((kk + u) * 4 + tg) * 8;
                uint4 kr0 = *(const uint4*)(k2p);
                uint4 kr1 = *(const uint4*)(k2p + 4);
                const unsigned kh[8] = {kr0.x, kr0.y, kr0.z, kr0.w,
                                        kr1.x, kr1.y, kr1.z, kr1.w};
                unsigned aa[4][4];
#pragma unroll
                for (int kc = 0; kc < 4; ++kc) {
                    __half2 p0 = u2h2(kh[kc * 2]);
                    __half2 p1 = u2h2(kh[kc * 2 + 1]);
                    aa[kc][0] = hmul2u(qa[kc][0], p0);
                    aa[kc][1] = hmul2u(qa[kc][1], p0);
                    aa[kc][2] = hmul2u(qa[kc][2], p1);
                    aa[kc][3] = hmul2u(qa[kc][3], p1);
                }
#pragma unroll
                for (int nt = 0; nt < 4; ++nt)
#pragma unroll
                    for (int r = 0; r < 4; ++r) sc[u][nt][r] = -M_LOG2;
#pragma unroll
                for (int kc = 0; kc < 4; ++kc)
#pragma unroll
                    for (int nt = 0; nt < 4; ++nt)
                        mma16816(sc[u][nt], aa[kc][0], aa[kc][1],
                                 aa[kc][2], aa[kc][3],
                                 bsf[kc][nt][0], bsf[kc][nt][1]);
            }

            unsigned pa[2][2][4];
#pragma unroll
            for (int u = 0; u < 2; ++u)
#pragma unroll
                for (int kc = 0; kc < 2; ++kc) {
                    pa[u][kc][0] = p2exp(sc[u][2 * kc][0],     sc[u][2 * kc][1]);
                    pa[u][kc][1] = p2exp(sc[u][2 * kc][2],     sc[u][2 * kc][3]);
                    pa[u][kc][2] = p2exp(sc[u][2 * kc + 1][0], sc[u][2 * kc + 1][1]);
                    pa[u][kc][3] = p2exp(sc[u][2 * kc + 1][2], sc[u][2 * kc + 1][3]);
                }

            // ---- l accumulation on ALU/FMA pipes (no tensor ops) ----------
#pragma unroll
            for (int u = 0; u < 2; ++u) {
                __half2 r0 = __hadd2(u2h2(pa[u][0][0]), u2h2(pa[u][0][2]));
                __half2 r1 = __hadd2(u2h2(pa[u][1][0]), u2h2(pa[u][1][2]));
                float2 f0  = __half22float2(__hadd2(r0, r1));
                l0 += f0.x + f0.y;
                __half2 s0 = __hadd2(u2h2(pa[u][0][1]), u2h2(pa[u][0][3]));
                __half2 s1 = __hadd2(u2h2(pa[u][1][1]), u2h2(pa[u][1][3]));
                float2 f1  = __half22float2(__hadd2(s0, s1));
                l1 += f1.x + f1.y;
            }

#pragma unroll
            for (int u = 0; u < 2; ++u) {
                const __half* v2p = v2t + (size_t)((kk + u) * 8 + g) * 8;
                uint4 vraw = *(const uint4*)(v2p);
                const unsigned vhp[4] = {vraw.x, vraw.y, vraw.z, vraw.w};
#pragma unroll
                for (int nt = 0; nt < 8; ++nt) {
                    __half2 pair = u2h2(vhp[nt >> 1]);
                    __half2 vdd  = (nt & 1) ? __high2half2(pair)
                                            : __low2half2(pair);
#pragma unroll
                    for (int kc = 0; kc < 2; ++kc) {
                        unsigned b0 = hmul2u(bvf[kc][nt][0], vdd);
                        unsigned b1 = hmul2u(bvf[kc][nt][1], vdd);
                        mma16816(pv[nt], pa[u][kc][0], pa[u][kc][1],
                                 pa[u][kc][2], pa[u][kc][3], b0, b1);
                    }
                }
            }
        }
    }

    // ---- epilogue: quad-reduce l over tg lanes, write partials -------------
    l0 += __shfl_xor_sync(0xffffffffu, l0, 1);
    l0 += __shfl_xor_sync(0xffffffffu, l0, 2);
    l1 += __shfl_xor_sync(0xffffffffu, l1, 1);
    l1 += __shfl_xor_sync(0xffffffffu, l1, 2);

    const int row0 = bh * SEQ + i0 + warp * 16 + g;
    const int row1 = row0 + 8;
    const int p0   = split * BHD * SEQ + row0;
    const int p1   = split * BHD * SEQ + row1;
    if (tg == 0) {
        pl[p0] = l0;
        pl[p1] = l1;
    }
#pragma unroll
    for (int nt = 0; nt < 8; ++nt) {
        int d = nt * 8 + 2 * tg;
        *(float2*)(pacc + (size_t)p0 * DH + d) = make_float2(pv[nt][0], pv[nt][1]);
        *(float2*)(pacc + (size_t)p1 * DH + d) = make_float2(pv[nt][2], pv[nt][3]);
    }
}

// ---------------------------------------------------------------------------
// Combine KSPLIT partials; write attn as fp16 hi/lo at [b,n,h*64+d].
// ---------------------------------------------------------------------------
__global__ __launch_bounds__(256) void combine_kernel(
    const float* __restrict__ pacc, const float* __restrict__ pl,
    __half* __restrict__ ahi, __half* __restrict__ alo)
{
    const int row = blockIdx.x * 4 + (threadIdx.x >> 6);
    const int d   = threadIdx.x & 63;

    float den = 0.f, num = 0.f;
#pragma unroll
    for (int s = 0; s < KSPLIT; ++s) {
        int idx = s * BHD * SEQ + row;
        den += pl[idx];
        num += pacc[(size_t)idx * DH + d];
    }
    float a = num / den;

    const int bh = row / SEQ, n = row % SEQ;
    const int b = bh >> 3, h = bh & 7;
    const int o = (b * SEQ + n) * DIMM + h * DH + d;
    __half hi = __float2half_rn(a);
    ahi[o] = hi;
    alo[o] = __float2half_rn(a - __half2float(hi));
}

// ---------------------------------------------------------------------------
extern "C" void kernel_launch(void* const* d_in, const int* in_sizes, int n_in,
                              void* d_out, int out_size)
{
    (void)in_sizes; (void)n_in; (void)out_size;
    const float* tokens = (const float*)d_in[0];
    const float* w_qkv  = (const float*)d_in[1];
    const float* w_out  = (const float*)d_in[2];
    const float* qw     = (const float*)d_in[3];
    const float* k1w    = (const float*)d_in[4];
    const float* k2w    = (const float*)d_in[5];
    const float* v1w    = (const float*)d_in[6];
    const float* v2w    = (const float*)d_in[7];
    float* out = (float*)d_out;

    float *pacc, *plv;
    __half *hq, *hk1, *hk2, *hv1, *hv2;
    __half *th, *tl, *wqh, *wql, *woh, *wol, *ah, *al;
    cudaGetSymbolAddress((void**)&hq,   g_hq);
    cudaGetSymbolAddress((void**)&hk1,  g_hk1);
    cudaGetSymbolAddress((void**)&hk2,  g_hk2);
    cudaGetSymbolAddress((void**)&hv1,  g_hv1);
    cudaGetSymbolAddress((void**)&hv2,  g_hv2);
    cudaGetSymbolAddress((void**)&pacc, g_pacc);
    cudaGetSymbolAddress((void**)&plv,  g_pl);
    cudaGetSymbolAddress((void**)&th,   g_th);
    cudaGetSymbolAddress((void**)&tl,   g_tl);
    cudaGetSymbolAddress((void**)&wqh,  g_wqh);
    cudaGetSymbolAddress((void**)&wql,  g_wql);
    cudaGetSymbolAddress((void**)&woh,  g_woh);
    cudaGetSymbolAddress((void**)&wol,  g_wol);
    cudaGetSymbolAddress((void**)&ah,   g_ah);
    cudaGetSymbolAddress((void**)&al,   g_al);

    cudaFuncSetAttribute(attn_mma,
                         cudaFuncAttributeMaxDynamicSharedMemorySize,
                         ATTN_SMEM_BYTES);

    // 0) fused hi/lo splits of GEMM operands
    split3_fp16<<<(N0Q + N1Q + N2Q + 255) / 256, 256>>>(
        tokens, th, tl, w_qkv, wqh, wql, w_out, woh, wol);
    // 1) qkv GEMM + fused rmsnorm -> fp16 q/k1/k2/v1/v2 [bh, n, 64]
    gemm_qkv_rms<<<dim3(QKV_C / 64, ROWS / 64), 256>>>(
        th, tl, wqh, wql, qw, k1w, k2w, v1w, v2w, hq, hk1, hk2, hv1, hv2);
    // 2) tensor-core 2-simplicial attention, static-max split-K (6 splits)
    attn_mma<<<dim3(KSPLIT, SEQ / ITILE, BHD), NTHR, ATTN_SMEM_BYTES>>>(
        hq, hk1, hk2, hv1, hv2, pacc, plv);
    // 3) combine partials -> attn hi/lo
    combine_kernel<<<BHD * SEQ / 4, 256>>>(pacc, plv, ah, al);
    // 4) out = attn @ w_out^T : [384,512]
    gemm_nt_tch<<<dim3(DIMM / 64, ROWS / 64), 256>>>(ah, al, woh, wol, out,
                                                     ROWS, DIMM, DIMM);
}

// round 15
// speedup vs baseline: 1.0504x; 1.0021x over previous
#include <cuda_runtime.h>
#include <cuda_fp16.h>
#include <math_constants.h>
#include <cstdint>

// ---------------------------------------------------------------------------
// HigherOrderAttention — R15 (over R14):
//   * combine_kernel: 2 rows/thread (2x memory-level parallelism, grid /2)
//   Everything else byte-identical to R14 (119.5 us baseline).
// ---------------------------------------------------------------------------

#define TOK_B   2
#define SEQ     192
#define DIMM    512
#define HEADS   8
#define DH      64
#define BHD     (TOK_B * HEADS)        // 16
#define QKV_C   2560
#define ROWS    (TOK_B * SEQ)          // 384
#define KSPLIT  6
#define KRANGE  (SEQ / KSPLIT)         // 32
#define ITILE   64
#define NWARP   4
#define NTHR    (NWARP * 32)           // 128
#define NJC     (SEQ / 32)             // 6

#define M_LOG2  7.2134752f             // 5 * log2(e)
#define QSCALE  0.18033688f            // 0.125 * log2(e)

// Scratch (device globals)
__device__ __half g_hq  [BHD * SEQ * DH];
__device__ __half g_hk1 [BHD * SEQ * DH];
__device__ __half g_hk2 [BHD * SEQ * DH];
__device__ __half g_hv1 [BHD * SEQ * DH];
__device__ __half g_hv2 [BHD * SEQ * DH];
__device__ float  g_pacc[KSPLIT * BHD * SEQ * DH];
__device__ float  g_pl  [KSPLIT * BHD * SEQ];
__device__ __half g_th  [ROWS * DIMM],  g_tl  [ROWS * DIMM];
__device__ __half g_wqh [QKV_C * DIMM], g_wql [QKV_C * DIMM];
__device__ __half g_woh [DIMM * DIMM],  g_wol [DIMM * DIMM];
__device__ __half g_ah  [ROWS * DIMM],  g_al  [ROWS * DIMM];

// ---------------------------------------------------------------------------
__device__ __forceinline__ void mma16816(float c[4],
                                         unsigned a0, unsigned a1,
                                         unsigned a2, unsigned a3,
                                         unsigned b0, unsigned b1)
{
    asm volatile(
        "mma.sync.aligned.m16n8k16.row.col.f32.f16.f16.f32 "
        "{%0,%1,%2,%3},{%4,%5,%6,%7},{%8,%9},{%0,%1,%2,%3};\n"
        : "+f"(c[0]), "+f"(c[1]), "+f"(c[2]), "+f"(c[3])
        : "r"(a0), "r"(a1), "r"(a2), "r"(a3), "r"(b0), "r"(b1));
}

__device__ __forceinline__ void ldsm_x4(unsigned r[4], const __half* p)
{
    unsigned sa = (unsigned)__cvta_generic_to_shared(p);
    asm volatile("ldmatrix.sync.aligned.m8n8.x4.shared.b16 {%0,%1,%2,%3}, [%4];"
                 : "=r"(r[0]), "=r"(r[1]), "=r"(r[2]), "=r"(r[3]) : "r"(sa));
}

__device__ __forceinline__ unsigned hmul2u(unsigned a, __half2 b)
{
    __half2 av = *reinterpret_cast<__half2*>(&a);
    __half2 r  = __hmul2(av, b);
    return *reinterpret_cast<unsigned*>(&r);
}

__device__ __forceinline__ __half2 u2h2(unsigned a)
{
    return *reinterpret_cast<__half2*>(&a);
}

__device__ __forceinline__ unsigned p2exp(float a, float b)
{
    __half2 h = __floats2half2_rn(a, b);
    unsigned x = *reinterpret_cast<unsigned*>(&h);
    unsigned r;
    asm("ex2.approx.f16x2 %0, %1;" : "=r"(r) : "r"(x));
    return r;
}

// ---------------------------------------------------------------------------
// Fused fp32 -> (hi,lo) fp16 split for 3 arrays.
// ---------------------------------------------------------------------------
__device__ __forceinline__ void split_quad(const float* __restrict__ x,
                                           __half* __restrict__ hi,
                                           __half* __restrict__ lo, int i)
{
    float4 v = ((const float4*)x)[i];
    __half hx = __float2half_rn(v.x), hy = __float2half_rn(v.y);
    __half hz = __float2half_rn(v.z), hw = __float2half_rn(v.w);
    ((__half2*)hi)[2 * i]     = __halves2half2(hx, hy);
    ((__half2*)hi)[2 * i + 1] = __halves2half2(hz, hw);
    ((__half2*)lo)[2 * i]     = __halves2half2(
        __float2half_rn(v.x - __half2float(hx)),
        __float2half_rn(v.y - __half2float(hy)));
    ((__half2*)lo)[2 * i + 1] = __halves2half2(
        __float2half_rn(v.z - __half2float(hz)),
        __float2half_rn(v.w - __half2float(hw)));
}

#define N0Q (ROWS * DIMM / 4)
#define N1Q (QKV_C * DIMM / 4)
#define N2Q (DIMM * DIMM / 4)

__global__ __launch_bounds__(256) void split3_fp16(
    const float* __restrict__ x0, __half* __restrict__ h0, __half* __restrict__ l0,
    const float* __restrict__ x1, __half* __restrict__ h1, __half* __restrict__ l1,
    const float* __restrict__ x2, __half* __restrict__ h2, __half* __restrict__ l2)
{
    int i = blockIdx.x * 256 + threadIdx.x;
    if (i < N0Q) {
        split_quad(x0, h0, l0, i);
    } else if (i < N0Q + N1Q) {
        split_quad(x1, h1, l1, i - N0Q);
    } else if (i < N0Q + N1Q + N2Q) {
        split_quad(x2, h2, l2, i - N0Q - N1Q);
    }
}

// ---------------------------------------------------------------------------
// Shared GEMM mainloop (64x64 tile, hi/lo fp16 operands, ldmatrix + double
// buffer). Produces per-thread c[4][4].
// ---------------------------------------------------------------------------
#define GS 40   // smem row stride in halves

struct GemmCtx {
    int wm, wn, g, tg;
};

__device__ __forceinline__ void gemm_mainloop(
    __half* smbase,                     // [2][4][64*GS]
    const __half* Ah_, const __half* Al_,
    const __half* Bh_, const __half* Bl_,
    int m0, int n0, int K, float c[4][4], GemmCtx& cx)
{
    const int t    = threadIdx.x;
    const int warp = t >> 5;
    const int lane = t & 31;
    cx.g  = lane >> 2;
    cx.tg = lane & 3;
    cx.wm = warp >> 1;
    cx.wn = warp & 1;

    const int lrow = t >> 2;
    const int lc8  = (t & 3) * 8;

    const int a_off = (cx.wm * 16 + (lane & 15)) * GS + 8 * (lane >> 4);
    const int b_row = cx.wn * 32 + (lane & 7) + ((lane >> 4) & 1) * 8;
    const int b_c8  = ((lane >> 3) & 1) * 8;

#pragma unroll
    for (int a = 0; a < 4; ++a)
#pragma unroll
        for (int b = 0; b < 4; ++b) c[a][b] = 0.f;

    const int NIT = K >> 5;
    const int BUF = 4 * 64 * GS;
    uint4 ra, rb, rc, rd;

    {
        size_t ga = (size_t)(m0 + lrow) * K + lc8;
        size_t gb = (size_t)(n0 + lrow) * K + lc8;
        ra = *(const uint4*)(Ah_ + ga);
        rb = *(const uint4*)(Al_ + ga);
        rc = *(const uint4*)(Bh_ + gb);
        rd = *(const uint4*)(Bl_ + gb);
        __half* p = smbase + lrow * GS + lc8;
        *(uint4*)(p)               = ra;
        *(uint4*)(p + 64 * GS)     = rb;
        *(uint4*)(p + 2 * 64 * GS) = rc;
        *(uint4*)(p + 3 * 64 * GS) = rd;
    }
    __syncthreads();

#pragma unroll 1
    for (int it = 0; it < NIT; ++it) {
        const int cur = it & 1;

        if (it + 1 < NIT) {
            size_t ga = (size_t)(m0 + lrow) * K + (it + 1) * 32 + lc8;
            size_t gb = (size_t)(n0 + lrow) * K + (it + 1) * 32 + lc8;
            ra = *(const uint4*)(Ah_ + ga);
            rb = *(const uint4*)(Al_ + ga);
            rc = *(const uint4*)(Bh_ + gb);
            rd = *(const uint4*)(Bl_ + gb);
        }

        const __half* Ahs = smbase + cur * BUF;
        const __half* Als = Ahs + 64 * GS;
        const __half* Bhs = Ahs + 2 * 64 * GS;
        const __half* Bls = Ahs + 3 * 64 * GS;

#pragma unroll
        for (int kc = 0; kc < 2; ++kc) {
            const int ko = kc * 16;
            unsigned ah[4], al[4];
            ldsm_x4(ah, Ahs + a_off + ko);
            ldsm_x4(al, Als + a_off + ko);
#pragma unroll
            for (int p = 0; p < 2; ++p) {
                unsigned bh[4], bl[4];
                const int bo = (b_row + p * 16) * GS + ko + b_c8;
                ldsm_x4(bh, Bhs + bo);
                ldsm_x4(bl, Bls + bo);
                mma16816(c[2 * p],     ah[0], ah[1], ah[2], ah[3], bh[0], bh[1]);
                mma16816(c[2 * p],     ah[0], ah[1], ah[2], ah[3], bl[0], bl[1]);
                mma16816(c[2 * p],     al[0], al[1], al[2], al[3], bh[0], bh[1]);
                mma16816(c[2 * p + 1], ah[0], ah[1], ah[2], ah[3], bh[2], bh[3]);
                mma16816(c[2 * p + 1], ah[0], ah[1], ah[2], ah[3], bl[2], bl[3]);
                mma16816(c[2 * p + 1], al[0], al[1], al[2], al[3], bh[2], bh[3]);
            }
        }

        if (it + 1 < NIT) {
            __half* p = smbase + (cur ^ 1) * BUF + lrow * GS + lc8;
            *(uint4*)(p)               = ra;
            *(uint4*)(p + 64 * GS)     = rb;
            *(uint4*)(p + 2 * 64 * GS) = rc;
            *(uint4*)(p + 3 * 64 * GS) = rd;
            __syncthreads();
        }
    }
}

// ---------------------------------------------------------------------------
// Plain NT GEMM (output projection): C fp32 to global.
// ---------------------------------------------------------------------------
__global__ __launch_bounds__(256) void gemm_nt_tch(
    const __half* __restrict__ Ah_, const __half* __restrict__ Al_,
    const __half* __restrict__ Bh_, const __half* __restrict__ Bl_,
    float* __restrict__ C, int M, int N, int K)
{
    __shared__ __half sm[2][4][64 * GS];
    float c[4][4];
    GemmCtx cx;
    gemm_mainloop(&sm[0][0][0], Ah_, Al_, Bh_, Bl_,
                  blockIdx.y * 64, blockIdx.x * 64, K, c, cx);

    const int row0 = blockIdx.y * 64 + cx.wm * 16 + cx.g;
    const int row1 = row0 + 8;
#pragma unroll
    for (int nt = 0; nt < 4; ++nt) {
        const int col = blockIdx.x * 64 + cx.wn * 32 + nt * 8 + 2 * cx.tg;
        *(float2*)(C + (size_t)row0 * N + col) = make_float2(c[nt][0], c[nt][1]);
        *(float2*)(C + (size_t)row1 * N + col) = make_float2(c[nt][2], c[nt][3]);
    }
}

// ---------------------------------------------------------------------------
// QKV GEMM with fused rmsnorm epilogue (identical to R14).
// ---------------------------------------------------------------------------
__global__ __launch_bounds__(256) void gemm_qkv_rms(
    const __half* __restrict__ Ah_, const __half* __restrict__ Al_,
    const __half* __restrict__ Bh_, const __half* __restrict__ Bl_,
    const float* __restrict__ qw,  const float* __restrict__ k1w,
    const float* __restrict__ k2w, const float* __restrict__ v1w,
    const float* __restrict__ v2w,
    __half* __restrict__ hq,  __half* __restrict__ hk1, __half* __restrict__ hk2,
    __half* __restrict__ hv1, __half* __restrict__ hv2)
{
    __shared__ __half sm[2][4][64 * GS];
    float c[4][4];
    GemmCtx cx;
    const int m0 = blockIdx.y * 64;
    const int n0 = blockIdx.x * 64;
    gemm_mainloop(&sm[0][0][0], Ah_, Al_, Bh_, Bl_, m0, n0, DIMM, c, cx);

    __syncthreads();
    float* smf = (float*)&sm[0][0][0];
#pragma unroll
    for (int nt = 0; nt < 4; ++nt) {
        const int col  = cx.wn * 32 + nt * 8 + 2 * cx.tg;
        const int row0 = cx.wm * 16 + cx.g;
        *(float2*)(smf + row0 * 68 + col)       = make_float2(c[nt][0], c[nt][1]);
        *(float2*)(smf + (row0 + 8) * 68 + col) = make_float2(c[nt][2], c[nt][3]);
    }
    __syncthreads();

    __half* dst;
    const float* w;
    float scale = 1.0f;
    int h;
    if (n0 < 512) {
        h = n0 >> 6;  dst = hq;  w = qw;  scale = QSCALE;
    } else if (n0 < 1536) {
        int off = n0 - 512;
        h = off >> 7;
        dst = (off & 64) ? hk2 : hk1;
        w   = (off & 64) ? k2w : k1w;
    } else {
        int off = n0 - 1536;
        h = off >> 7;
        dst = (off & 64) ? hv2 : hv1;
        w   = (off & 64) ? v2w : v1w;
    }

    const int warp = threadIdx.x >> 5;
    const int lane = threadIdx.x & 31;
    const float w0 = w[lane];
    const float w1 = w[lane + 32];

#pragma unroll
    for (int rr = 0; rr < 8; ++rr) {
        const int r    = warp * 8 + rr;
        const int grow = m0 + r;
        const int b    = grow / SEQ;
        const int n    = grow % SEQ;

        float x0 = smf[r * 68 + lane];
        float x1 = smf[r * 68 + lane + 32];
        float ss = x0 * x0 + x1 * x1;
#pragma unroll
        for (int o = 16; o >= 1; o >>= 1)
            ss += __shfl_xor_sync(0xffffffffu, ss, o);
        float inv = rsqrtf(ss * (1.0f / 64.0f) + 1.1920929e-07f) * scale;

        __half* yp = dst + ((size_t)(b * HEADS + h) * SEQ + n) * DH;
        yp[lane]      = __float2half(x0 * inv * w0);
        yp[lane + 32] = __float2half(x1 * inv * w1);
    }
}

// ---------------------------------------------------------------------------
// Tensor-core attention (identical to R14).
// ---------------------------------------------------------------------------
#define K1_STRIDE 72
#define SM_K1   (SEQ * K1_STRIDE)
#define SM_V1T  (DH * 200)
#define SM_Q    (ITILE * DH)
#define SM_K2   (KRANGE * DH)
#define SM_V2   (KRANGE * DH)
#define ATTN_SMEM_HALVES (SM_K1 + SM_V1T + SM_Q + SM_K2 + SM_V2)
#define ATTN_SMEM_BYTES  (ATTN_SMEM_HALVES * 2)

__global__ __launch_bounds__(NTHR, 2) void attn_mma(
    const __half* __restrict__ hq,  const __half* __restrict__ hk1,
    const __half* __restrict__ hk2, const __half* __restrict__ hv1,
    const __half* __restrict__ hv2,
    float* __restrict__ pacc, float* __restrict__ pl)
{
    extern __shared__ __align__(16) __half smh[];
    __half*  k1s  = smh;
    __half*  v1t  = k1s + SM_K1;
    __half*  qs   = v1t + SM_V1T;
    __half2* k2t2 = (__half2*)(qs + SM_Q);
    __half*  v2t  = qs + SM_Q + SM_K2;

    const int split = blockIdx.x;
    const int i0    = blockIdx.y * ITILE;
    const int bh    = blockIdx.z;
    const int t     = threadIdx.x;
    const int kbeg  = split * KRANGE;

    const __half* k1b = hk1 + bh * SEQ * DH;
    const __half* v1b = hv1 + bh * SEQ * DH;
    const __half* k2b = hk2 + (bh * SEQ + kbeg) * DH;
    const __half* v2b = hv2 + (bh * SEQ + kbeg) * DH;
    const __half* qb  = hq  + (bh * SEQ + i0) * DH;

    // ---- vectorized prologue ----------------------------------------------
    for (int e = t; e < SEQ * DH / 8; e += NTHR) {
        int j = e >> 3, c8 = (e & 7) * 8;
        *(uint4*)(k1s + j * K1_STRIDE + c8) = *(const uint4*)(k1b + j * DH + c8);
        uint4 vv = *(const uint4*)(v1b + j * DH + c8);
        const __half* vh = (const __half*)&vv;
#pragma unroll
        for (int m = 0; m < 8; ++m)
            v1t[(c8 + m) * 200 + j] = vh[m];
    }
    for (int e = t; e < ITILE * DH / 8; e += NTHR)
        ((uint4*)qs)[e] = ((const uint4*)qb)[e];
    for (int e = t; e < KRANGE * 32; e += NTHR) {
        int kk = e >> 5, r = e & 31;
        int tg_ = r >> 3, s = r & 7;
        int col = (s >> 1) * 16 + (s & 1) * 8 + tg_ * 2;
        k2t2[e] = *(const __half2*)(k2b + kk * DH + col);
    }
    for (int e = t; e < KRANGE * 8; e += NTHR) {
        int kk = e >> 3, g_ = e & 7;
        __half tmp[8];
#pragma unroll
        for (int nt = 0; nt < 8; ++nt)
            tmp[nt] = v2b[kk * DH + nt * 8 + g_];
        *(uint4*)(v2t + e * 8) = *(const uint4*)tmp;
    }
    __syncthreads();

    const int warp = t >> 5;
    const int lane = t & 31;
    const int g    = lane >> 2;
    const int tg   = lane & 3;

    const int l7   = lane & 7;
    const int c8b  = ((lane >> 3) & 1) * 8;
    const int ntp  = (lane >> 4) & 1;

    unsigned qa[4][4];
    {
        const __half* qr0 = qs + (warp * 16 + g) * DH;
        const __half* qr8 = qs + (warp * 16 + g + 8) * DH;
#pragma unroll
        for (int kc = 0; kc < 4; ++kc) {
            qa[kc][0] = *(const unsigned*)(qr0 + kc * 16 + 2 * tg);
            qa[kc][1] = *(const unsigned*)(qr8 + kc * 16 + 2 * tg);
            qa[kc][2] = *(const unsigned*)(qr0 + kc * 16 + 2 * tg + 8);
            qa[kc][3] = *(const unsigned*)(qr8 + kc * 16 + 2 * tg + 8);
        }
    }

    float pv[8][4];
#pragma unroll
    for (int n = 0; n < 8; ++n)
#pragma unroll
        for (int r = 0; r < 4; ++r) pv[n][r] = 0.f;
    float l0 = 0.f, l1 = 0.f;

#pragma unroll 1
    for (int jc = 0; jc < NJC; ++jc) {
        unsigned bsf[4][4][2];
        unsigned bvf[2][8][2];
#pragma unroll
        for (int kc = 0; kc < 4; ++kc)
#pragma unroll
            for (int np = 0; np < 2; ++np) {
                unsigned r4[4];
                const __half* p = k1s
                    + (jc * 32 + (np * 2 + ntp) * 8 + l7) * K1_STRIDE
                    + kc * 16 + c8b;
                ldsm_x4(r4, p);
                bsf[kc][2 * np][0]     = r4[0];
                bsf[kc][2 * np][1]     = r4[1];
                bsf[kc][2 * np + 1][0] = r4[2];
                bsf[kc][2 * np + 1][1] = r4[3];
            }
#pragma unroll
        for (int kc = 0; kc < 2; ++kc)
#pragma unroll
            for (int np = 0; np < 4; ++np) {
                unsigned r4[4];
                const __half* p = v1t
                    + ((np * 2 + ntp) * 8 + l7) * 200
                    + jc * 32 + kc * 16 + c8b;
                ldsm_x4(r4, p);
                bvf[kc][2 * np][0]     = r4[0];
                bvf[kc][2 * np][1]     = r4[1];
                bvf[kc][2 * np + 1][0] = r4[2];
                bvf[kc][2 * np + 1][1] = r4[3];
            }

#pragma unroll 1
        for (int kk = 0; kk < KRANGE; kk += 2) {
            float sc[2][4][4];
#pragma unroll
            for (int u = 0; u < 2; ++u) {
                const __half2* k2p = k2t2 + (size_t)((kk + u) * 4 + tg) * 8;
                uint4 kr0 = *(const uint4*)(k2p);
                uint4 kr1 = *(const uint4*)(k2p + 4);
                const unsigned kh[8] = {kr0.x, kr0.y, kr0.z, kr0.w,
                                        kr1.x, kr1.y, kr1.z, kr1.w};
                unsigned aa[4][4];
#pragma unroll
                for (int kc = 0; kc < 4; ++kc) {
                    __half2 p0 = u2h2(kh[kc * 2]);
                    __half2 p1 = u2h2(kh[kc * 2 + 1]);
                    aa[kc][0] = hmul2u(qa[kc][0], p0);
                    aa[kc][1] = hmul2u(qa[kc][1], p0);
                    aa[kc][2] = hmul2u(qa[kc][2], p1);
                    aa[kc][3] = hmul2u(qa[kc][3], p1);
                }
#pragma unroll
                for (int nt = 0; nt < 4; ++nt)
#pragma unroll
                    for (int r = 0; r < 4; ++r) sc[u][nt][r] = -M_LOG2;
#pragma unroll
                for (int kc = 0; kc < 4; ++kc)
#pragma unroll
                    for (int nt = 0; nt < 4; ++nt)
                        mma16816(sc[u][nt], aa[kc][0], aa[kc][1],
                                 aa[kc][2], aa[kc][3],
                                 bsf[kc][nt][0], bsf[kc][nt][1]);
            }

            unsigned pa[2][2][4];
#pragma unroll
            for (int u = 0; u < 2; ++u)
#pragma unroll
                for (int kc = 0; kc < 2; ++kc) {
                    pa[u][kc][0] = p2exp(sc[u][2 * kc][0],     sc[u][2 * kc][1]);
                    pa[u][kc][1] = p2exp(sc[u][2 * kc][2],     sc[u][2 * kc][3]);
                    pa[u][kc][2] = p2exp(sc[u][2 * kc + 1][0], sc[u][2 * kc + 1][1]);
                    pa[u][kc][3] = p2exp(sc[u][2 * kc + 1][2], sc[u][2 * kc + 1][3]);
                }

            // ---- l accumulation on ALU/FMA pipes ---------------------------
#pragma unroll
            for (int u = 0; u < 2; ++u) {
                __half2 r0 = __hadd2(u2h2(pa[u][0][0]), u2h2(pa[u][0][2]));
                __half2 r1 = __hadd2(u2h2(pa[u][1][0]), u2h2(pa[u][1][2]));
                float2 f0  = __half22float2(__hadd2(r0, r1));
                l0 += f0.x + f0.y;
                __half2 s0 = __hadd2(u2h2(pa[u][0][1]), u2h2(pa[u][0][3]));
                __half2 s1 = __hadd2(u2h2(pa[u][1][1]), u2h2(pa[u][1][3]));
                float2 f1  = __half22float2(__hadd2(s0, s1));
                l1 += f1.x + f1.y;
            }

#pragma unroll
            for (int u = 0; u < 2; ++u) {
                const __half* v2p = v2t + (size_t)((kk + u) * 8 + g) * 8;
                uint4 vraw = *(const uint4*)(v2p);
                const unsigned vhp[4] = {vraw.x, vraw.y, vraw.z, vraw.w};
#pragma unroll
                for (int nt = 0; nt < 8; ++nt) {
                    __half2 pair = u2h2(vhp[nt >> 1]);
                    __half2 vdd  = (nt & 1) ? __high2half2(pair)
                                            : __low2half2(pair);
#pragma unroll
                    for (int kc = 0; kc < 2; ++kc) {
                        unsigned b0 = hmul2u(bvf[kc][nt][0], vdd);
                        unsigned b1 = hmul2u(bvf[kc][nt][1], vdd);
                        mma16816(pv[nt], pa[u][kc][0], pa[u][kc][1],
                                 pa[u][kc][2], pa[u][kc][3], b0, b1);
                    }
                }
            }
        }
    }

    // ---- epilogue: quad-reduce l over tg lanes, write partials -------------
    l0 += __shfl_xor_sync(0xffffffffu, l0, 1);
    l0 += __shfl_xor_sync(0xffffffffu, l0, 2);
    l1 += __shfl_xor_sync(0xffffffffu, l1, 1);
    l1 += __shfl_xor_sync(0xffffffffu, l1, 2);

    const int row0 = bh * SEQ + i0 + warp * 16 + g;
    const int row1 = row0 + 8;
    const int p0   = split * BHD * SEQ + row0;
    const int p1   = split * BHD * SEQ + row1;
    if (tg == 0) {
        pl[p0] = l0;
        pl[p1] = l1;
    }
#pragma unroll
    for (int nt = 0; nt < 8; ++nt) {
        int d = nt * 8 + 2 * tg;
        *(float2*)(pacc + (size_t)p0 * DH + d) = make_float2(pv[nt][0], pv[nt][1]);
        *(float2*)(pacc + (size_t)p1 * DH + d) = make_float2(pv[nt][2], pv[nt][3]);
    }
}

// ---------------------------------------------------------------------------
// Combine KSPLIT partials; 2 rows per thread for 2x MLP (L2-latency bound).
// Writes attn as fp16 hi/lo at [b,n,h*64+d].
// ---------------------------------------------------------------------------
__global__ __launch_bounds__(256) void combine_kernel(
    const float* __restrict__ pacc, const float* __restrict__ pl,
    __half* __restrict__ ahi, __half* __restrict__ alo)
{
    const int r0 = blockIdx.x * 8 + (threadIdx.x >> 6) * 2;  // rows r0, r0+1
    const int d  = threadIdx.x & 63;

    float den0 = 0.f, num0 = 0.f, den1 = 0.f, num1 = 0.f;
#pragma unroll
    for (int s = 0; s < KSPLIT; ++s) {
        int idx = s * BHD * SEQ + r0;
        den0 += pl[idx];
        den1 += pl[idx + 1];
        num0 += pacc[(size_t)idx * DH + d];
        num1 += pacc[(size_t)(idx + 1) * DH + d];
    }
    float a0 = num0 / den0;
    float a1 = num1 / den1;

    // rows r0, r0+1 share bh (SEQ even, r0 even): n0 = r0%SEQ, n1 = n0+1
    const int bh = r0 / SEQ, n = r0 % SEQ;
    const int b = bh >> 3, h = bh & 7;
    const size_t o0 = (size_t)(b * SEQ + n) * DIMM + h * DH + d;
    const size_t o1 = o0 + DIMM;

    __half h0 = __float2half_rn(a0);
    __half h1 = __float2half_rn(a1);
    ahi[o0] = h0;
    alo[o0] = __float2half_rn(a0 - __half2float(h0));
    ahi[o1] = h1;
    alo[o1] = __float2half_rn(a1 - __half2float(h1));
}

// ---------------------------------------------------------------------------
extern "C" void kernel_launch(void* const* d_in, const int* in_sizes, int n_in,
                              void* d_out, int out_size)
{
    (void)in_sizes; (void)n_in; (void)out_size;
    const float* tokens = (const float*)d_in[0];
    const float* w_qkv  = (const float*)d_in[1];
    const float* w_out  = (const float*)d_in[2];
    const float* qw     = (const float*)d_in[3];
    const float* k1w    = (const float*)d_in[4];
    const float* k2w    = (const float*)d_in[5];
    const float* v1w    = (const float*)d_in[6];
    const float* v2w    = (const float*)d_in[7];
    float* out = (float*)d_out;

    float *pacc, *plv;
    __half *hq, *hk1, *hk2, *hv1, *hv2;
    __half *th, *tl, *wqh, *wql, *woh, *wol, *ah, *al;
    cudaGetSymbolAddress((void**)&hq,   g_hq);
    cudaGetSymbolAddress((void**)&hk1,  g_hk1);
    cudaGetSymbolAddress((void**)&hk2,  g_hk2);
    cudaGetSymbolAddress((void**)&hv1,  g_hv1);
    cudaGetSymbolAddress((void**)&hv2,  g_hv2);
    cudaGetSymbolAddress((void**)&pacc, g_pacc);
    cudaGetSymbolAddress((void**)&plv,  g_pl);
    cudaGetSymbolAddress((void**)&th,   g_th);
    cudaGetSymbolAddress((void**)&tl,   g_tl);
    cudaGetSymbolAddress((void**)&wqh,  g_wqh);
    cudaGetSymbolAddress((void**)&wql,  g_wql);
    cudaGetSymbolAddress((void**)&woh,  g_woh);
    cudaGetSymbolAddress((void**)&wol,  g_wol);
    cudaGetSymbolAddress((void**)&ah,   g_ah);
    cudaGetSymbolAddress((void**)&al,   g_al);

    cudaFuncSetAttribute(attn_mma,
                         cudaFuncAttributeMaxDynamicSharedMemorySize,
                         ATTN_SMEM_BYTES);

    // 0) fused hi/lo splits of GEMM operands
    split3_fp16<<<(N0Q + N1Q + N2Q + 255) / 256, 256>>>(
        tokens, th, tl, w_qkv, wqh, wql, w_out, woh, wol);
    // 1) qkv GEMM + fused rmsnorm -> fp16 q/k1/k2/v1/v2 [bh, n, 64]
    gemm_qkv_rms<<<dim3(QKV_C / 64, ROWS / 64), 256>>>(
        th, tl, wqh, wql, qw, k1w, k2w, v1w, v2w, hq, hk1, hk2, hv1, hv2);
    // 2) tensor-core 2-simplicial attention, static-max split-K (6 splits)
    attn_mma<<<dim3(KSPLIT, SEQ / ITILE, BHD), NTHR, ATTN_SMEM_BYTES>>>(
        hq, hk1, hk2, hv1, hv2, pacc, plv);
    // 3) combine partials -> attn hi/lo (2 rows/thread)
    combine_kernel<<<BHD * SEQ / 8, 256>>>(pacc, plv, ah, al);
    // 4) out = attn @ w_out^T : [384,512]
    gemm_nt_tch<<<dim3(DIMM / 64, ROWS / 64), 256>>>(ah, al, woh, wol, out,
                                                     ROWS, DIMM, DIMM);
}

// round 16
// speedup vs baseline: 1.0708x; 1.0194x over previous
#include <cuda_runtime.h>
#include <cuda_fp16.h>
#include <math_constants.h>
#include <cstdint>

// ---------------------------------------------------------------------------
// HigherOrderAttention — R16 (over R15):
//   * attn: 256-thread blocks = 2 splits sharing k1/v1/q smem (one prologue
//     per SM instead of two; grid 288 -> 144, single clean wave)
//   * split3 -> split2 (tokens+w_qkv); w_out split folded into combine
//   Math byte-identical to R15.
// ---------------------------------------------------------------------------

#define TOK_B   2
#define SEQ     192
#define DIMM    512
#define HEADS   8
#define DH      64
#define BHD     (TOK_B * HEADS)        // 16
#define QKV_C   2560
#define ROWS    (TOK_B * SEQ)          // 384
#define KSPLIT  6
#define KRANGE  (SEQ / KSPLIT)         // 32
#define ITILE   64
#define NTHR    256                    // 8 warps = 2 split-halves x 4 warps
#define NJC     (SEQ / 32)             // 6

#define M_LOG2  7.2134752f             // 5 * log2(e)
#define QSCALE  0.18033688f            // 0.125 * log2(e)

// Scratch (device globals)
__device__ __half g_hq  [BHD * SEQ * DH];
__device__ __half g_hk1 [BHD * SEQ * DH];
__device__ __half g_hk2 [BHD * SEQ * DH];
__device__ __half g_hv1 [BHD * SEQ * DH];
__device__ __half g_hv2 [BHD * SEQ * DH];
__device__ float  g_pacc[KSPLIT * BHD * SEQ * DH];
__device__ float  g_pl  [KSPLIT * BHD * SEQ];
__device__ __half g_th  [ROWS * DIMM],  g_tl  [ROWS * DIMM];
__device__ __half g_wqh [QKV_C * DIMM], g_wql [QKV_C * DIMM];
__device__ __half g_woh [DIMM * DIMM],  g_wol [DIMM * DIMM];
__device__ __half g_ah  [ROWS * DIMM],  g_al  [ROWS * DIMM];

// ---------------------------------------------------------------------------
__device__ __forceinline__ void mma16816(float c[4],
                                         unsigned a0, unsigned a1,
                                         unsigned a2, unsigned a3,
                                         unsigned b0, unsigned b1)
{
    asm volatile(
        "mma.sync.aligned.m16n8k16.row.col.f32.f16.f16.f32 "
        "{%0,%1,%2,%3},{%4,%5,%6,%7},{%8,%9},{%0,%1,%2,%3};\n"
        : "+f"(c[0]), "+f"(c[1]), "+f"(c[2]), "+f"(c[3])
        : "r"(a0), "r"(a1), "r"(a2), "r"(a3), "r"(b0), "r"(b1));
}

__device__ __forceinline__ void ldsm_x4(unsigned r[4], const __half* p)
{
    unsigned sa = (unsigned)__cvta_generic_to_shared(p);
    asm volatile("ldmatrix.sync.aligned.m8n8.x4.shared.b16 {%0,%1,%2,%3}, [%4];"
                 : "=r"(r[0]), "=r"(r[1]), "=r"(r[2]), "=r"(r[3]) : "r"(sa));
}

__device__ __forceinline__ unsigned hmul2u(unsigned a, __half2 b)
{
    __half2 av = *reinterpret_cast<__half2*>(&a);
    __half2 r  = __hmul2(av, b);
    return *reinterpret_cast<unsigned*>(&r);
}

__device__ __forceinline__ __half2 u2h2(unsigned a)
{
    return *reinterpret_cast<__half2*>(&a);
}

__device__ __forceinline__ unsigned p2exp(float a, float b)
{
    __half2 h = __floats2half2_rn(a, b);
    unsigned x = *reinterpret_cast<unsigned*>(&h);
    unsigned r;
    asm("ex2.approx.f16x2 %0, %1;" : "=r"(r) : "r"(x));
    return r;
}

// ---------------------------------------------------------------------------
// fp32 -> (hi,lo) fp16 split helper.
// ---------------------------------------------------------------------------
__device__ __forceinline__ void split_quad(const float* __restrict__ x,
                                           __half* __restrict__ hi,
                                           __half* __restrict__ lo, int i)
{
    float4 v = ((const float4*)x)[i];
    __half hx = __float2half_rn(v.x), hy = __float2half_rn(v.y);
    __half hz = __float2half_rn(v.z), hw = __float2half_rn(v.w);
    ((__half2*)hi)[2 * i]     = __halves2half2(hx, hy);
    ((__half2*)hi)[2 * i + 1] = __halves2half2(hz, hw);
    ((__half2*)lo)[2 * i]     = __halves2half2(
        __float2half_rn(v.x - __half2float(hx)),
        __float2half_rn(v.y - __half2float(hy)));
    ((__half2*)lo)[2 * i + 1] = __halves2half2(
        __float2half_rn(v.z - __half2float(hz)),
        __float2half_rn(v.w - __half2float(hw)));
}

#define N0Q (ROWS * DIMM / 4)
#define N1Q (QKV_C * DIMM / 4)
#define N2Q (DIMM * DIMM / 4)

// tokens + w_qkv only (critical path into QKV GEMM)
__global__ __launch_bounds__(256) void split2_fp16(
    const float* __restrict__ x0, __half* __restrict__ h0, __half* __restrict__ l0,
    const float* __restrict__ x1, __half* __restrict__ h1, __half* __restrict__ l1)
{
    int i = blockIdx.x * 256 + threadIdx.x;
    if (i < N0Q) {
        split_quad(x0, h0, l0, i);
    } else if (i < N0Q + N1Q) {
        split_quad(x1, h1, l1, i - N0Q);
    }
}

// ---------------------------------------------------------------------------
// Shared GEMM mainloop (64x64 tile, hi/lo fp16 operands, ldmatrix + double
// buffer).
// ---------------------------------------------------------------------------
#define GS 40   // smem row stride in halves

struct GemmCtx {
    int wm, wn, g, tg;
};

__device__ __forceinline__ void gemm_mainloop(
    __half* smbase,                     // [2][4][64*GS]
    const __half* Ah_, const __half* Al_,
    const __half* Bh_, const __half* Bl_,
    int m0, int n0, int K, float c[4][4], GemmCtx& cx)
{
    const int t    = threadIdx.x;
    const int warp = t >> 5;
    const int lane = t & 31;
    cx.g  = lane >> 2;
    cx.tg = lane & 3;
    cx.wm = warp >> 1;
    cx.wn = warp & 1;

    const int lrow = t >> 2;
    const int lc8  = (t & 3) * 8;

    const int a_off = (cx.wm * 16 + (lane & 15)) * GS + 8 * (lane >> 4);
    const int b_row = cx.wn * 32 + (lane & 7) + ((lane >> 4) & 1) * 8;
    const int b_c8  = ((lane >> 3) & 1) * 8;

#pragma unroll
    for (int a = 0; a < 4; ++a)
#pragma unroll
        for (int b = 0; b < 4; ++b) c[a][b] = 0.f;

    const int NIT = K >> 5;
    const int BUF = 4 * 64 * GS;
    uint4 ra, rb, rc, rd;

    {
        size_t ga = (size_t)(m0 + lrow) * K + lc8;
        size_t gb = (size_t)(n0 + lrow) * K + lc8;
        ra = *(const uint4*)(Ah_ + ga);
        rb = *(const uint4*)(Al_ + ga);
        rc = *(const uint4*)(Bh_ + gb);
        rd = *(const uint4*)(Bl_ + gb);
        __half* p = smbase + lrow * GS + lc8;
        *(uint4*)(p)               = ra;
        *(uint4*)(p + 64 * GS)     = rb;
        *(uint4*)(p + 2 * 64 * GS) = rc;
        *(uint4*)(p + 3 * 64 * GS) = rd;
    }
    __syncthreads();

#pragma unroll 1
    for (int it = 0; it < NIT; ++it) {
        const int cur = it & 1;

        if (it + 1 < NIT) {
            size_t ga = (size_t)(m0 + lrow) * K + (it + 1) * 32 + lc8;
            size_t gb = (size_t)(n0 + lrow) * K + (it + 1) * 32 + lc8;
            ra = *(const uint4*)(Ah_ + ga);
            rb = *(const uint4*)(Al_ + ga);
            rc = *(const uint4*)(Bh_ + gb);
            rd = *(const uint4*)(Bl_ + gb);
        }

        const __half* Ahs = smbase + cur * BUF;
        const __half* Als = Ahs + 64 * GS;
        const __half* Bhs = Ahs + 2 * 64 * GS;
        const __half* Bls = Ahs + 3 * 64 * GS;

#pragma unroll
        for (int kc = 0; kc < 2; ++kc) {
            const int ko = kc * 16;
            unsigned ah[4], al[4];
            ldsm_x4(ah, Ahs + a_off + ko);
            ldsm_x4(al, Als + a_off + ko);
#pragma unroll
            for (int p = 0; p < 2; ++p) {
                unsigned bh[4], bl[4];
                const int bo = (b_row + p * 16) * GS + ko + b_c8;
                ldsm_x4(bh, Bhs + bo);
                ldsm_x4(bl, Bls + bo);
                mma16816(c[2 * p],     ah[0], ah[1], ah[2], ah[3], bh[0], bh[1]);
                mma16816(c[2 * p],     ah[0], ah[1], ah[2], ah[3], bl[0], bl[1]);
                mma16816(c[2 * p],     al[0], al[1], al[2], al[3], bh[0], bh[1]);
                mma16816(c[2 * p + 1], ah[0], ah[1], ah[2], ah[3], bh[2], bh[3]);
                mma16816(c[2 * p + 1], ah[0], ah[1], ah[2], ah[3], bl[2], bl[3]);
                mma16816(c[2 * p + 1], al[0], al[1], al[2], al[3], bh[2], bh[3]);
            }
        }

        if (it + 1 < NIT) {
            __half* p = smbase + (cur ^ 1) * BUF + lrow * GS + lc8;
            *(uint4*)(p)               = ra;
            *(uint4*)(p + 64 * GS)     = rb;
            *(uint4*)(p + 2 * 64 * GS) = rc;
            *(uint4*)(p + 3 * 64 * GS) = rd;
            __syncthreads();
        }
    }
}

// ---------------------------------------------------------------------------
// Plain NT GEMM (output projection): C fp32 to global.
// ---------------------------------------------------------------------------
__global__ __launch_bounds__(256) void gemm_nt_tch(
    const __half* __restrict__ Ah_, const __half* __restrict__ Al_,
    const __half* __restrict__ Bh_, const __half* __restrict__ Bl_,
    float* __restrict__ C, int M, int N, int K)
{
    __shared__ __half sm[2][4][64 * GS];
    float c[4][4];
    GemmCtx cx;
    gemm_mainloop(&sm[0][0][0], Ah_, Al_, Bh_, Bl_,
                  blockIdx.y * 64, blockIdx.x * 64, K, c, cx);

    const int row0 = blockIdx.y * 64 + cx.wm * 16 + cx.g;
    const int row1 = row0 + 8;
#pragma unroll
    for (int nt = 0; nt < 4; ++nt) {
        const int col = blockIdx.x * 64 + cx.wn * 32 + nt * 8 + 2 * cx.tg;
        *(float2*)(C + (size_t)row0 * N + col) = make_float2(c[nt][0], c[nt][1]);
        *(float2*)(C + (size_t)row1 * N + col) = make_float2(c[nt][2], c[nt][3]);
    }
}

// ---------------------------------------------------------------------------
// QKV GEMM with fused rmsnorm epilogue (identical to R15).
// ---------------------------------------------------------------------------
__global__ __launch_bounds__(256) void gemm_qkv_rms(
    const __half* __restrict__ Ah_, const __half* __restrict__ Al_,
    const __half* __restrict__ Bh_, const __half* __restrict__ Bl_,
    const float* __restrict__ qw,  const float* __restrict__ k1w,
    const float* __restrict__ k2w, const float* __restrict__ v1w,
    const float* __restrict__ v2w,
    __half* __restrict__ hq,  __half* __restrict__ hk1, __half* __restrict__ hk2,
    __half* __restrict__ hv1, __half* __restrict__ hv2)
{
    __shared__ __half sm[2][4][64 * GS];
    float c[4][4];
    GemmCtx cx;
    const int m0 = blockIdx.y * 64;
    const int n0 = blockIdx.x * 64;
    gemm_mainloop(&sm[0][0][0], Ah_, Al_, Bh_, Bl_, m0, n0, DIMM, c, cx);

    __syncthreads();
    float* smf = (float*)&sm[0][0][0];
#pragma unroll
    for (int nt = 0; nt < 4; ++nt) {
        const int col  = cx.wn * 32 + nt * 8 + 2 * cx.tg;
        const int row0 = cx.wm * 16 + cx.g;
        *(float2*)(smf + row0 * 68 + col)       = make_float2(c[nt][0], c[nt][1]);
        *(float2*)(smf + (row0 + 8) * 68 + col) = make_float2(c[nt][2], c[nt][3]);
    }
    __syncthreads();

    __half* dst;
    const float* w;
    float scale = 1.0f;
    int h;
    if (n0 < 512) {
        h = n0 >> 6;  dst = hq;  w = qw;  scale = QSCALE;
    } else if (n0 < 1536) {
        int off = n0 - 512;
        h = off >> 7;
        dst = (off & 64) ? hk2 : hk1;
        w   = (off & 64) ? k2w : k1w;
    } else {
        int off = n0 - 1536;
        h = off >> 7;
        dst = (off & 64) ? hv2 : hv1;
        w   = (off & 64) ? v2w : v1w;
    }

    const int warp = threadIdx.x >> 5;
    const int lane = threadIdx.x & 31;
    const float w0 = w[lane];
    const float w1 = w[lane + 32];

#pragma unroll
    for (int rr = 0; rr < 8; ++rr) {
        const int r    = warp * 8 + rr;
        const int grow = m0 + r;
        const int b    = grow / SEQ;
        const int n    = grow % SEQ;

        float x0 = smf[r * 68 + lane];
        float x1 = smf[r * 68 + lane + 32];
        float ss = x0 * x0 + x1 * x1;
#pragma unroll
        for (int o = 16; o >= 1; o >>= 1)
            ss += __shfl_xor_sync(0xffffffffu, ss, o);
        float inv = rsqrtf(ss * (1.0f / 64.0f) + 1.1920929e-07f) * scale;

        __half* yp = dst + ((size_t)(b * HEADS + h) * SEQ + n) * DH;
        yp[lane]      = __float2half(x0 * inv * w0);
        yp[lane + 32] = __float2half(x1 * inv * w1);
    }
}

// ---------------------------------------------------------------------------
// Tensor-core attention: 256-thread blocks, 2 splits per block sharing the
// k1/v1/q smem tiles. Per-warp math identical to R15.
// ---------------------------------------------------------------------------
#define K1_STRIDE 72
#define SM_K1   (SEQ * K1_STRIDE)      // 13824
#define SM_V1T  (DH * 200)             // 12800
#define SM_Q    (ITILE * DH)           //  4096
#define SM_K2H  (KRANGE * DH)          //  2048 per half
#define SM_V2H  (KRANGE * DH)          //  2048 per half
#define ATTN_SMEM_HALVES (SM_K1 + SM_V1T + SM_Q + 2 * (SM_K2H + SM_V2H))
#define ATTN_SMEM_BYTES  (ATTN_SMEM_HALVES * 2)   // 77824 B

__global__ __launch_bounds__(NTHR, 1) void attn_mma(
    const __half* __restrict__ hq,  const __half* __restrict__ hk1,
    const __half* __restrict__ hk2, const __half* __restrict__ hv1,
    const __half* __restrict__ hv2,
    float* __restrict__ pacc, float* __restrict__ pl)
{
    extern __shared__ __align__(16) __half smh[];
    __half*  k1s  = smh;                              // shared
    __half*  v1t  = k1s + SM_K1;                      // shared
    __half*  qs   = v1t + SM_V1T;                     // shared
    __half2* k2t2 = (__half2*)(qs + SM_Q);            // [2][KRANGE*32] half2
    __half*  v2t  = qs + SM_Q + 2 * SM_K2H;           // [2][KRANGE*64]

    const int i0   = blockIdx.y * ITILE;
    const int bh   = blockIdx.z;
    const int t    = threadIdx.x;

    const __half* k1b = hk1 + bh * SEQ * DH;
    const __half* v1b = hv1 + bh * SEQ * DH;
    const __half* qb  = hq  + (bh * SEQ + i0) * DH;

    // ---- prologue (one per SM, shared tiles loaded once) -------------------
    for (int e = t; e < SEQ * DH / 8; e += NTHR) {
        int j = e >> 3, c8 = (e & 7) * 8;
        *(uint4*)(k1s + j * K1_STRIDE + c8) = *(const uint4*)(k1b + j * DH + c8);
        uint4 vv = *(const uint4*)(v1b + j * DH + c8);
        const __half* vh = (const __half*)&vv;
#pragma unroll
        for (int m = 0; m < 8; ++m)
            v1t[(c8 + m) * 200 + j] = vh[m];
    }
    for (int e = t; e < ITILE * DH / 8; e += NTHR)
        ((uint4*)qs)[e] = ((const uint4*)qb)[e];
    // k2 relayout for both halves
    for (int e = t; e < 2 * KRANGE * 32; e += NTHR) {
        int hh  = e >> 10;                // half index
        int rem = e & 1023;
        int kk  = rem >> 5, r = rem & 31;
        int tg_ = r >> 3,   s = r & 7;
        int col = (s >> 1) * 16 + (s & 1) * 8 + tg_ * 2;
        const __half* k2b = hk2 +
            (bh * SEQ + (blockIdx.x * 2 + hh) * KRANGE) * DH;
        k2t2[e] = *(const __half2*)(k2b + kk * DH + col);
    }
    // v2 relayout for both halves
    for (int e = t; e < 2 * KRANGE * 8; e += NTHR) {
        int hh  = e >> 8;
        int rem = e & 255;
        int kk  = rem >> 3, g_ = rem & 7;
        const __half* v2b = hv2 +
            (bh * SEQ + (blockIdx.x * 2 + hh) * KRANGE) * DH;
        __half tmp[8];
#pragma unroll
        for (int nt = 0; nt < 8; ++nt)
            tmp[nt] = v2b[kk * DH + nt * 8 + g_];
        *(uint4*)(v2t + e * 8) = *(const uint4*)tmp;
    }
    __syncthreads();

    const int warp8 = t >> 5;            // 0..7
    const int half  = warp8 >> 2;        // 0/1 -> split pair member
    const int warp  = warp8 & 3;         // 0..3 (as in R15)
    const int split = blockIdx.x * 2 + half;
    const int lane  = t & 31;
    const int g     = lane >> 2;
    const int tg    = lane & 3;

    const int l7   = lane & 7;
    const int c8b  = ((lane >> 3) & 1) * 8;
    const int ntp  = (lane >> 4) & 1;

    const __half2* k2h = k2t2 + half * (KRANGE * 32);
    const __half*  v2h = v2t  + half * (KRANGE * 64);

    unsigned qa[4][4];
    {
        const __half* qr0 = qs + (warp * 16 + g) * DH;
        const __half* qr8 = qs + (warp * 16 + g + 8) * DH;
#pragma unroll
        for (int kc = 0; kc < 4; ++kc) {
            qa[kc][0] = *(const unsigned*)(qr0 + kc * 16 + 2 * tg);
            qa[kc][1] = *(const unsigned*)(qr8 + kc * 16 + 2 * tg);
            qa[kc][2] = *(const unsigned*)(qr0 + kc * 16 + 2 * tg + 8);
            qa[kc][3] = *(const unsigned*)(qr8 + kc * 16 + 2 * tg + 8);
        }
    }

    float pv[8][4];
#pragma unroll
    for (int n = 0; n < 8; ++n)
#pragma unroll
        for (int r = 0; r < 4; ++r) pv[n][r] = 0.f;
    float l0 = 0.f, l1 = 0.f;

#pragma unroll 1
    for (int jc = 0; jc < NJC; ++jc) {
        unsigned bsf[4][4][2];
        unsigned bvf[2][8][2];
#pragma unroll
        for (int kc = 0; kc < 4; ++kc)
#pragma unroll
            for (int np = 0; np < 2; ++np) {
                unsigned r4[4];
                const __half* p = k1s
                    + (jc * 32 + (np * 2 + ntp) * 8 + l7) * K1_STRIDE
                    + kc * 16 + c8b;
                ldsm_x4(r4, p);
                bsf[kc][2 * np][0]     = r4[0];
                bsf[kc][2 * np][1]     = r4[1];
                bsf[kc][2 * np + 1][0] = r4[2];
                bsf[kc][2 * np + 1][1] = r4[3];
            }
#pragma unroll
        for (int kc = 0; kc < 2; ++kc)
#pragma unroll
            for (int np = 0; np < 4; ++np) {
                unsigned r4[4];
                const __half* p = v1t
                    + ((np * 2 + ntp) * 8 + l7) * 200
                    + jc * 32 + kc * 16 + c8b;
                ldsm_x4(r4, p);
                bvf[kc][2 * np][0]     = r4[0];
                bvf[kc][2 * np][1]     = r4[1];
                bvf[kc][2 * np + 1][0] = r4[2];
                bvf[kc][2 * np + 1][1] = r4[3];
            }

#pragma unroll 1
        for (int kk = 0; kk < KRANGE; kk += 2) {
            float sc[2][4][4];
#pragma unroll
            for (int u = 0; u < 2; ++u) {
                const __half2* k2p = k2h + (size_t)((kk + u) * 4 + tg) * 8;
                uint4 kr0 = *(const uint4*)(k2p);
                uint4 kr1 = *(const uint4*)(k2p + 4);
                const unsigned kh[8] = {kr0.x, kr0.y, kr0.z, kr0.w,
                                        kr1.x, kr1.y, kr1.z, kr1.w};
                unsigned aa[4][4];
#pragma unroll
                for (int kc = 0; kc < 4; ++kc) {
                    __half2 p0 = u2h2(kh[kc * 2]);
                    __half2 p1 = u2h2(kh[kc * 2 + 1]);
                    aa[kc][0] = hmul2u(qa[kc][0], p0);
                    aa[kc][1] = hmul2u(qa[kc][1], p0);
                    aa[kc][2] = hmul2u(qa[kc][2], p1);
                    aa[kc][3] = hmul2u(qa[kc][3], p1);
                }
#pragma unroll
                for (int nt = 0; nt < 4; ++nt)
#pragma unroll
                    for (int r = 0; r < 4; ++r) sc[u][nt][r] = -M_LOG2;
#pragma unroll
                for (int kc = 0; kc < 4; ++kc)
#pragma unroll
                    for (int nt = 0; nt < 4; ++nt)
                        mma16816(sc[u][nt], aa[kc][0], aa[kc][1],
                                 aa[kc][2], aa[kc][3],
                                 bsf[kc][nt][0], bsf[kc][nt][1]);
            }

            unsigned pa[2][2][4];
#pragma unroll
            for (int u = 0; u < 2; ++u)
#pragma unroll
                for (int kc = 0; kc < 2; ++kc) {
                    pa[u][kc][0] = p2exp(sc[u][2 * kc][0],     sc[u][2 * kc][1]);
                    pa[u][kc][1] = p2exp(sc[u][2 * kc][2],     sc[u][2 * kc][3]);
                    pa[u][kc][2] = p2exp(sc[u][2 * kc + 1][0], sc[u][2 * kc + 1][1]);
                    pa[u][kc][3] = p2exp(sc[u][2 * kc + 1][2], sc[u][2 * kc + 1][3]);
                }

            // ---- l accumulation on ALU/FMA pipes ---------------------------
#pragma unroll
            for (int u = 0; u < 2; ++u) {
                __half2 r0 = __hadd2(u2h2(pa[u][0][0]), u2h2(pa[u][0][2]));
                __half2 r1 = __hadd2(u2h2(pa[u][1][0]), u2h2(pa[u][1][2]));
                float2 f0  = __half22float2(__hadd2(r0, r1));
                l0 += f0.x + f0.y;
                __half2 s0 = __hadd2(u2h2(pa[u][0][1]), u2h2(pa[u][0][3]));
                __half2 s1 = __hadd2(u2h2(pa[u][1][1]), u2h2(pa[u][1][3]));
                float2 f1  = __half22float2(__hadd2(s0, s1));
                l1 += f1.x + f1.y;
            }

#pragma unroll
            for (int u = 0; u < 2; ++u) {
                const __half* v2p = v2h + (size_t)((kk + u) * 8 + g) * 8;
                uint4 vraw = *(const uint4*)(v2p);
                const unsigned vhp[4] = {vraw.x, vraw.y, vraw.z, vraw.w};
#pragma unroll
                for (int nt = 0; nt < 8; ++nt) {
                    __half2 pair = u2h2(vhp[nt >> 1]);
                    __half2 vdd  = (nt & 1) ? __high2half2(pair)
                                            : __low2half2(pair);
#pragma unroll
                    for (int kc = 0; kc < 2; ++kc) {
                        unsigned b0 = hmul2u(bvf[kc][nt][0], vdd);
                        unsigned b1 = hmul2u(bvf[kc][nt][1], vdd);
                        mma16816(pv[nt], pa[u][kc][0], pa[u][kc][1],
                                 pa[u][kc][2], pa[u][kc][3], b0, b1);
                    }
                }
            }
        }
    }

    // ---- epilogue -----------------------------------------------------------
    l0 += __shfl_xor_sync(0xffffffffu, l0, 1);
    l0 += __shfl_xor_sync(0xffffffffu, l0, 2);
    l1 += __shfl_xor_sync(0xffffffffu, l1, 1);
    l1 += __shfl_xor_sync(0xffffffffu, l1, 2);

    const int row0 = bh * SEQ + i0 + warp * 16 + g;
    const int row1 = row0 + 8;
    const int p0   = split * BHD * SEQ + row0;
    const int p1   = split * BHD * SEQ + row1;
    if (tg == 0) {
        pl[p0] = l0;
        pl[p1] = l1;
    }
#pragma unroll
    for (int nt = 0; nt < 8; ++nt) {
        int d = nt * 8 + 2 * tg;
        *(float2*)(pacc + (size_t)p0 * DH + d) = make_float2(pv[nt][0], pv[nt][1]);
        *(float2*)(pacc + (size_t)p1 * DH + d) = make_float2(pv[nt][2], pv[nt][3]);
    }
}

// ---------------------------------------------------------------------------
// Combine KSPLIT partials (2 rows/thread) + w_out hi/lo split (folded in).
// ---------------------------------------------------------------------------
__global__ __launch_bounds__(256) void combine_kernel(
    const float* __restrict__ pacc, const float* __restrict__ pl,
    __half* __restrict__ ahi, __half* __restrict__ alo,
    const float* __restrict__ w_out,
    __half* __restrict__ woh, __half* __restrict__ wol)
{
    const int r0 = blockIdx.x * 8 + (threadIdx.x >> 6) * 2;  // rows r0, r0+1
    const int d  = threadIdx.x & 63;

    float den0 = 0.f, num0 = 0.f, den1 = 0.f, num1 = 0.f;
#pragma unroll
    for (int s = 0; s < KSPLIT; ++s) {
        int idx = s * BHD * SEQ + r0;
        den0 += pl[idx];
        den1 += pl[idx + 1];
        num0 += pacc[(size_t)idx * DH + d];
        num1 += pacc[(size_t)(idx + 1) * DH + d];
    }
    float a0 = num0 / den0;
    float a1 = num1 / den1;

    const int bh = r0 / SEQ, n = r0 % SEQ;
    const int b = bh >> 3, h = bh & 7;
    const size_t o0 = (size_t)(b * SEQ + n) * DIMM + h * DH + d;
    const size_t o1 = o0 + DIMM;

    __half h0 = __float2half_rn(a0);
    __half h1 = __float2half_rn(a1);
    ahi[o0] = h0;
    alo[o0] = __float2half_rn(a0 - __half2float(h0));
    ahi[o1] = h1;
    alo[o1] = __float2half_rn(a1 - __half2float(h1));

    // ---- w_out split (independent; needed only by the out GEMM) ------------
    const int gi = blockIdx.x * 256 + threadIdx.x;
    if (gi < N2Q)
        split_quad(w_out, woh, wol, gi);
}

// ---------------------------------------------------------------------------
extern "C" void kernel_launch(void* const* d_in, const int* in_sizes, int n_in,
                              void* d_out, int out_size)
{
    (void)in_sizes; (void)n_in; (void)out_size;
    const float* tokens = (const float*)d_in[0];
    const float* w_qkv  = (const float*)d_in[1];
    const float* w_out  = (const float*)d_in[2];
    const float* qw     = (const float*)d_in[3];
    const float* k1w    = (const float*)d_in[4];
    const float* k2w    = (const float*)d_in[5];
    const float* v1w    = (const float*)d_in[6];
    const float* v2w    = (const float*)d_in[7];
    float* out = (float*)d_out;

    float *pacc, *plv;
    __half *hq, *hk1, *hk2, *hv1, *hv2;
    __half *th, *tl, *wqh, *wql, *woh, *wol, *ah, *al;
    cudaGetSymbolAddress((void**)&hq,   g_hq);
    cudaGetSymbolAddress((void**)&hk1,  g_hk1);
    cudaGetSymbolAddress((void**)&hk2,  g_hk2);
    cudaGetSymbolAddress((void**)&hv1,  g_hv1);
    cudaGetSymbolAddress((void**)&hv2,  g_hv2);
    cudaGetSymbolAddress((void**)&pacc, g_pacc);
    cudaGetSymbolAddress((void**)&plv,  g_pl);
    cudaGetSymbolAddress((void**)&th,   g_th);
    cudaGetSymbolAddress((void**)&tl,   g_tl);
    cudaGetSymbolAddress((void**)&wqh,  g_wqh);
    cudaGetSymbolAddress((void**)&wql,  g_wql);
    cudaGetSymbolAddress((void**)&woh,  g_woh);
    cudaGetSymbolAddress((void**)&wol,  g_wol);
    cudaGetSymbolAddress((void**)&ah,   g_ah);
    cudaGetSymbolAddress((void**)&al,   g_al);

    cudaFuncSetAttribute(attn_mma,
                         cudaFuncAttributeMaxDynamicSharedMemorySize,
                         ATTN_SMEM_BYTES);

    // 0) hi/lo splits of tokens + w_qkv (critical path)
    split2_fp16<<<(N0Q + N1Q + 255) / 256, 256>>>(tokens, th, tl,
                                                  w_qkv, wqh, wql);
    // 1) qkv GEMM + fused rmsnorm -> fp16 q/k1/k2/v1/v2 [bh, n, 64]
    gemm_qkv_rms<<<dim3(QKV_C / 64, ROWS / 64), 256>>>(
        th, tl, wqh, wql, qw, k1w, k2w, v1w, v2w, hq, hk1, hk2, hv1, hv2);
    // 2) attention: 144 blocks, 2 splits/block, shared k1/v1/q tiles
    attn_mma<<<dim3(KSPLIT / 2, SEQ / ITILE, BHD), NTHR, ATTN_SMEM_BYTES>>>(
        hq, hk1, hk2, hv1, hv2, pacc, plv);
    // 3) combine partials -> attn hi/lo (+ w_out split folded in)
    combine_kernel<<<BHD * SEQ / 8, 256>>>(pacc, plv, ah, al,
                                           w_out, woh, wol);
    // 4) out = attn @ w_out^T : [384,512]
    gemm_nt_tch<<<dim3(DIMM / 64, ROWS / 64), 256>>>(ah, al, woh, wol, out,
                                                     ROWS, DIMM, DIMM);
}